// round 13
// baseline (speedup 1.0000x reference)
#include <cuda_runtime.h>

// ---------------- problem constants ----------------
constexpr int NB  = 256;   // batch
constexpr int NL  = 16;    // max length
constexpr int NH  = 512;   // LSTM hidden
constexpr int ND2 = 1024;  // 2*NH
constexpr int NG4 = 2048;  // 4*NH (lstm gates) == 2*ND2
constexpr int NG5 = 5120;  // 5*ND2 (tree gates)
constexpr int NSLOT = 31;  // 16 initial + 15 created slots (stable ids)
constexpr int RSPLIT = 4;  // recurrent GEMM split-K
constexpr int ISPLIT = 4;  // incremental GEMM split-K
constexpr int DUMMY_ROW = NB * NSLOT;   // padding target row

// ---------------- scratch layout ----------------
constexpr long SZ_XREV  = (long)NB * NL * NH;
constexpr long SZ_XG    = (long)NB * NL * NG4;
constexpr long SZ_GPART = (long)2 * RSPLIT * NB * NG4;
constexpr long SZ_ST    = (long)NB * NH;
constexpr long SZ_SEQ   = (long)NB * NL * NH;
constexpr long SZ_SLOT  = (long)NB * NSLOT * ND2;        // h_slot / c_slot / nh / nc
constexpr long SZ_P     = (long)(NB * NSLOT + 1) * NG5;  // PL / PR (+1 dummy row)
constexpr long SZ_LG    = (long)NB * NSLOT;
constexpr long SZ_VPART = (long)2 * ISPLIT * NB * NG5;

constexpr long OFF_XREV   = 0;
constexpr long OFF_XG_F   = OFF_XREV + SZ_XREV;
constexpr long OFF_XG_B   = OFF_XG_F + SZ_XG;
constexpr long OFF_GPART  = OFF_XG_B + SZ_XG;
constexpr long OFF_HST    = OFF_GPART + SZ_GPART;   // 4 states: h_f, h_b, c_f, c_b
constexpr long OFF_HSEQ_F = OFF_HST + 4 * SZ_ST;
constexpr long OFF_HSEQ_B = OFF_HSEQ_F + SZ_SEQ;
constexpr long OFF_CSEQ_F = OFF_HSEQ_B + SZ_SEQ;
constexpr long OFF_CSEQ_B = OFF_CSEQ_F + SZ_SEQ;
// h_slot, c_slot, nh, nc MUST be contiguous in this order: the rowOf indirection
// relies on  h_slot + 2*SZ_SLOT == nh  and  c_slot + 2*SZ_SLOT == nc.
constexpr long OFF_HSLOT  = OFF_CSEQ_B + SZ_SEQ;
constexpr long OFF_CSLOT  = OFF_HSLOT + SZ_SLOT;
constexpr long OFF_NH     = OFF_CSLOT + SZ_SLOT;
constexpr long OFF_NC     = OFF_NH + SZ_SLOT;
constexpr long OFF_PL     = OFF_NC + SZ_SLOT;
constexpr long OFF_PR     = OFF_PL + SZ_P;
constexpr long OFF_LG     = OFF_PR + SZ_P;
constexpr long OFF_VPART  = OFF_LG + SZ_LG;
constexpr long TOTAL_F    = OFF_VPART + SZ_VPART;

constexpr int ROW_CACHE_BASE = 2 * NB * NSLOT;   // nh/nc rows start here (relative to h_slot/c_slot)

__device__ float g_buf[TOTAL_F];
__device__ int   g_slotpos[NB * 16];     // position -> slot id
__device__ int   g_done[NB];
__device__ int   g_lid[NB];              // left-neighbor slot id for recompute pair (or -1)
__device__ int   g_rid[NB];              // right-neighbor slot id for recompute pair (or -1)
__device__ int   g_rowOf[NB * NSLOT];    // slot id -> data row (h_slot/c_slot base)
__device__ int   g_rowPL[NB * 16];       // iter-0 gathered rows, PL side (m < len-1)
__device__ int   g_rowPR[NB * 16];       // iter-0 gathered rows, PR side (1 <= m < len)
__device__ int   g_actlist[NB];          // compacted active batch ids
__device__ int   g_actrows[NB];          // compacted active data rows (for inc GEMM A gather)
__device__ int   g_misc[4];              // [0]=nrPad128, [1]=nact, [2]=nactPad128, [3]=nactPad64

__device__ __forceinline__ float sigm(float x) { return 1.0f / (1.0f + expf(-x)); }

// ---------------- generic fp32 SGEMM body (double-buffered, KB=16, scalar FFMA) ----------------
// C[row, col] = sum_{k in [kbeg,kend)} Arow(row)[k] * W[col, k]  (+ bias[col])
// Tiles 128x128x16, 8x8 per-thread, 256 threads. (kend-kbeg) multiple of 16.
__device__ __forceinline__
void sgemm_body(const float* __restrict__ A, int P, long strideB, long strideM,
                const int* __restrict__ rowA,
                const float* __restrict__ W, int wstride, int kbeg, int kend,
                const float* __restrict__ bias,
                float* __restrict__ C, int N, long coStrideB,
                const int* __restrict__ rowC)
{
    __shared__ float As[2][16][128];
    __shared__ float Bs[2][16][128];
    const int tid = threadIdx.x;
    const int rowBase = blockIdx.y * 128;
    const int colBase = blockIdx.x * 128;
    const int tx = tid & 15;
    const int ty = tid >> 4;
    const int lr = tid >> 1;          // load row within tile (0..127)
    const int lk = (tid & 1) * 4;     // k offset (0 or 4); second half at +8

    const int r = rowBase + lr;
    const float* aPtr;
    if (rowA) {
        aPtr = A + (long)rowA[r] * strideM + kbeg + lk;
    } else {
        const int bidx = r / P;
        aPtr = A + (long)bidx * strideB + (long)(r - bidx * P) * strideM + kbeg + lk;
    }
    const float* wPtr = W + (long)(colBase + lr) * wstride + kbeg + lk;

    float acc[8][8];
#pragma unroll
    for (int i = 0; i < 8; i++)
#pragma unroll
        for (int j = 0; j < 8; j++) acc[i][j] = 0.0f;

    const int nk = (kend - kbeg) / 16;
    float4 av0 = *reinterpret_cast<const float4*>(aPtr);
    float4 av1 = *reinterpret_cast<const float4*>(aPtr + 8);
    float4 bv0 = *reinterpret_cast<const float4*>(wPtr);
    float4 bv1 = *reinterpret_cast<const float4*>(wPtr + 8);
    int buf = 0;

    for (int it = 0; it < nk; it++) {
        As[buf][lk + 0][lr] = av0.x; As[buf][lk + 1][lr] = av0.y;
        As[buf][lk + 2][lr] = av0.z; As[buf][lk + 3][lr] = av0.w;
        As[buf][lk + 8][lr] = av1.x; As[buf][lk + 9][lr] = av1.y;
        As[buf][lk + 10][lr] = av1.z; As[buf][lk + 11][lr] = av1.w;
        Bs[buf][lk + 0][lr] = bv0.x; Bs[buf][lk + 1][lr] = bv0.y;
        Bs[buf][lk + 2][lr] = bv0.z; Bs[buf][lk + 3][lr] = bv0.w;
        Bs[buf][lk + 8][lr] = bv1.x; Bs[buf][lk + 9][lr] = bv1.y;
        Bs[buf][lk + 10][lr] = bv1.z; Bs[buf][lk + 11][lr] = bv1.w;
        __syncthreads();
        if (it + 1 < nk) {
            const int kb = (it + 1) * 16;
            av0 = *reinterpret_cast<const float4*>(aPtr + kb);
            av1 = *reinterpret_cast<const float4*>(aPtr + kb + 8);
            bv0 = *reinterpret_cast<const float4*>(wPtr + kb);
            bv1 = *reinterpret_cast<const float4*>(wPtr + kb + 8);
        }
#pragma unroll
        for (int kk = 0; kk < 16; kk++) {
            float4 a0 = *reinterpret_cast<const float4*>(&As[buf][kk][ty * 8]);
            float4 a1 = *reinterpret_cast<const float4*>(&As[buf][kk][ty * 8 + 4]);
            float4 b0 = *reinterpret_cast<const float4*>(&Bs[buf][kk][tx * 8]);
            float4 b1 = *reinterpret_cast<const float4*>(&Bs[buf][kk][tx * 8 + 4]);
            float ra[8] = {a0.x, a0.y, a0.z, a0.w, a1.x, a1.y, a1.z, a1.w};
            float rb[8] = {b0.x, b0.y, b0.z, b0.w, b1.x, b1.y, b1.z, b1.w};
#pragma unroll
            for (int i = 0; i < 8; i++)
#pragma unroll
                for (int j = 0; j < 8; j++)
                    acc[i][j] += ra[i] * rb[j];
        }
        buf ^= 1;
    }

#pragma unroll
    for (int i = 0; i < 8; i++) {
        const int row = rowBase + ty * 8 + i;
        long rOff;
        if (rowC) {
            rOff = (long)rowC[row] * N;
        } else {
            const int ob = row / P;
            rOff = (long)ob * coStrideB + (long)(row - ob * P) * N;
        }
#pragma unroll
        for (int j = 0; j < 8; j += 4) {
            const int col = colBase + tx * 8 + j;
            float4 v;
            v.x = acc[i][j]; v.y = acc[i][j + 1]; v.z = acc[i][j + 2]; v.w = acc[i][j + 3];
            if (bias) {
                v.x += bias[col]; v.y += bias[col + 1];
                v.z += bias[col + 2]; v.w += bias[col + 3];
            }
            *reinterpret_cast<float4*>(C + rOff + col) = v;
        }
    }
}

// ---------------- 64-row tile variant (64x128x16, 4x8 per-thread) ----------------
// Same kk-order inside each 16-wide k chunk as sgemm_body -> per-output FMA
// sequence identical -> bit-identical results. Used for the incremental GEMM
// where the active row count is small (reduces M-padding waste to 64-granularity).
__device__ __forceinline__
void sgemm_body64(const float* __restrict__ A, long strideM,
                  const int* __restrict__ rowA,
                  const float* __restrict__ W, int wstride, int kbeg, int kend,
                  float* __restrict__ C, int N)
{
    __shared__ float As[2][16][64];
    __shared__ float Bs[2][16][128];
    const int tid = threadIdx.x;
    const int rowBase = blockIdx.y * 64;
    const int colBase = blockIdx.x * 128;
    const int tx = tid & 15;
    const int ty = tid >> 4;
    const int lra = tid >> 2;          // A load row (0..63)
    const int lka = (tid & 3) * 4;     // A k offset (0,4,8,12)
    const int lrb = tid >> 1;          // B load row (0..127)
    const int lkb = (tid & 1) * 4;     // B k offset (0 or 4); second half at +8

    const float* aPtr = A + (long)rowA[rowBase + lra] * strideM + kbeg + lka;
    const float* wPtr = W + (long)(colBase + lrb) * wstride + kbeg + lkb;

    float acc[4][8];
#pragma unroll
    for (int i = 0; i < 4; i++)
#pragma unroll
        for (int j = 0; j < 8; j++) acc[i][j] = 0.0f;

    const int nk = (kend - kbeg) / 16;
    float4 av = *reinterpret_cast<const float4*>(aPtr);
    float4 bv0 = *reinterpret_cast<const float4*>(wPtr);
    float4 bv1 = *reinterpret_cast<const float4*>(wPtr + 8);
    int buf = 0;

    for (int it = 0; it < nk; it++) {
        As[buf][lka + 0][lra] = av.x; As[buf][lka + 1][lra] = av.y;
        As[buf][lka + 2][lra] = av.z; As[buf][lka + 3][lra] = av.w;
        Bs[buf][lkb + 0][lrb] = bv0.x; Bs[buf][lkb + 1][lrb] = bv0.y;
        Bs[buf][lkb + 2][lrb] = bv0.z; Bs[buf][lkb + 3][lrb] = bv0.w;
        Bs[buf][lkb + 8][lrb] = bv1.x; Bs[buf][lkb + 9][lrb] = bv1.y;
        Bs[buf][lkb + 10][lrb] = bv1.z; Bs[buf][lkb + 11][lrb] = bv1.w;
        __syncthreads();
        if (it + 1 < nk) {
            const int kb = (it + 1) * 16;
            av = *reinterpret_cast<const float4*>(aPtr + kb);
            bv0 = *reinterpret_cast<const float4*>(wPtr + kb);
            bv1 = *reinterpret_cast<const float4*>(wPtr + kb + 8);
        }
#pragma unroll
        for (int kk = 0; kk < 16; kk++) {
            float4 a0 = *reinterpret_cast<const float4*>(&As[buf][kk][ty * 4]);
            float4 b0 = *reinterpret_cast<const float4*>(&Bs[buf][kk][tx * 8]);
            float4 b1 = *reinterpret_cast<const float4*>(&Bs[buf][kk][tx * 8 + 4]);
            float ra[4] = {a0.x, a0.y, a0.z, a0.w};
            float rb[8] = {b0.x, b0.y, b0.z, b0.w, b1.x, b1.y, b1.z, b1.w};
#pragma unroll
            for (int i = 0; i < 4; i++)
#pragma unroll
                for (int j = 0; j < 8; j++)
                    acc[i][j] += ra[i] * rb[j];
        }
        buf ^= 1;
    }

#pragma unroll
    for (int i = 0; i < 4; i++) {
        const long rOff = (long)(rowBase + ty * 4 + i) * N;
#pragma unroll
        for (int j = 0; j < 8; j += 4) {
            const int col = colBase + tx * 8 + j;
            float4 v;
            v.x = acc[i][j]; v.y = acc[i][j + 1]; v.z = acc[i][j + 2]; v.w = acc[i][j + 3];
            *reinterpret_cast<float4*>(C + rOff + col) = v;
        }
    }
}

// full input projections: z selects fwd/bwd (standalone, saturated; NOT fused with rec)
__global__ __launch_bounds__(256, 2)
void sgemm_proj_k(const float* __restrict__ A0, const float* __restrict__ A1,
                  const float* __restrict__ W0, const float* __restrict__ W1,
                  const float* __restrict__ b0, const float* __restrict__ b1,
                  float* __restrict__ C0, float* __restrict__ C1)
{
    if (blockIdx.z == 0)
        sgemm_body(A0, 1, NH, 0, nullptr, W0, NH, 0, NH, b0, C0, NG4, NG4, nullptr);
    else
        sgemm_body(A1, 1, NH, 0, nullptr, W1, NH, 0, NH, b1, C1, NG4, NG4, nullptr);
}

// recurrent: z = dir*RSPLIT + sp, K=512 split into 128-chunks, partials out
__global__ __launch_bounds__(256, 2)
void sgemm_rec_k(const float* __restrict__ hf, const float* __restrict__ hb,
                 const float* __restrict__ whf, const float* __restrict__ whb,
                 float* __restrict__ gpart)
{
    const int z = blockIdx.z;
    const int dir = z / RSPLIT;
    const int sp = z % RSPLIT;
    const int kb = sp * (NH / RSPLIT);
    sgemm_body(dir ? hb : hf, 1, NH, 0, nullptr, dir ? whb : whf, NH, kb, kb + NH / RSPLIT,
               nullptr, gpart + (long)z * NB * NG4, NG4, NG4, nullptr);
}

// iter-0 slot partials over per-side gathered rows. z = side (0=PL, 1=PR).
__global__ __launch_bounds__(256, 2)
void sgemm_slots0_k(const float* __restrict__ h_slot, const float* __restrict__ w_comp,
                    float* __restrict__ PL, float* __restrict__ PR,
                    const int* __restrict__ rowPL, const int* __restrict__ rowPR,
                    const int* __restrict__ misc)
{
    if (blockIdx.y * 128 >= misc[0]) return;
    const int side = blockIdx.z;
    const int* rows = side ? rowPR : rowPL;
    sgemm_body(h_slot, 1, 0, ND2, rows,
               w_comp + side * ND2, NG4, 0, ND2, nullptr,
               side ? PR : PL, NG5, 0, rows);
}

// incremental slot partials over compacted active rows — 64-row tiles.
__global__ __launch_bounds__(256, 2)
void sgemm_inc64_k(const float* __restrict__ h_slot, const float* __restrict__ w_comp,
                   float* __restrict__ vpart, const int* __restrict__ actrows,
                   const int* __restrict__ misc)
{
    if (blockIdx.y * 64 >= misc[3]) return;
    const int z = blockIdx.z;
    const int side = z / ISPLIT;
    const int sp = z % ISPLIT;
    const int kb = sp * (ND2 / ISPLIT);
    sgemm_body64(h_slot, ND2, actrows,
                 w_comp + side * ND2, NG4, kb, kb + ND2 / ISPLIT,
                 vpart + (long)z * NB * NG5, NG5);
}

// ---------------- helper kernels ----------------
__global__ void fill0_k(float* p, long n) {
    long i = (long)blockIdx.x * 256 + threadIdx.x;
    if (i < n) p[i] = 0.0f;
}

__global__ void rev_input_k(const float* __restrict__ x, const int* __restrict__ len,
                            float* __restrict__ xrev)
{
    int idx = blockIdx.x * 256 + threadIdx.x;        // NB*NL*NH
    int j = idx % NH;
    int t2 = idx / NH;
    int t = t2 % NL;
    int b = t2 / NL;
    int ln = len[b];
    int src = (t < ln) ? (ln - 1 - t) : t;
    xrev[idx] = x[((long)b * NL + src) * NH + j];
}

// fused fwd+bwd LSTM cell with split-K partial reduction
__global__ void lstm_cell2_k(const float* __restrict__ xgf, const float* __restrict__ xgb,
                             const float* __restrict__ gpart,
                             float* __restrict__ hf, float* __restrict__ hb,
                             float* __restrict__ cf, float* __restrict__ cb,
                             float* __restrict__ hsf, float* __restrict__ hsb,
                             float* __restrict__ csf, float* __restrict__ csb, int t)
{
    int gidx = blockIdx.x * 256 + threadIdx.x;       // 2*NB*NH
    int dir = gidx >= NB * NH;
    int idx = gidx - dir * NB * NH;
    int b = idx >> 9;
    int j = idx & (NH - 1);
    const float* xg = (dir ? xgb : xgf) + (long)b * NL * NG4;
    const float* gp = gpart + (long)dir * RSPLIT * NB * NG4 + (long)b * NG4;
    float g[4];
#pragma unroll
    for (int c4 = 0; c4 < 4; c4++) {
        int comp = c4 * NH + j;
        float s = xg[comp];
#pragma unroll
        for (int sp = 0; sp < RSPLIT; sp++)
            s += gp[(long)sp * NB * NG4 + comp];
        g[c4] = s;
    }
    float* hstate = dir ? hb : hf;
    float* cstate = dir ? cb : cf;
    float* hseq   = dir ? hsb : hsf;
    float* cseq   = dir ? csb : csf;
    float c = sigm(g[1]) * cstate[idx] + sigm(g[0]) * tanhf(g[2]);
    float h = sigm(g[3]) * tanhf(c);
    cstate[idx] = c;
    hstate[idx] = h;
    long s = ((long)b * NL + t) * NH + j;
    hseq[s] = h;
    cseq[s] = c;
}

// init slot h/c (slots 0..15 = leaf positions), position->slot map, leaf rowOf
__global__ void tree_init_k(const float* __restrict__ hseqf, const float* __restrict__ hseqb,
                            const float* __restrict__ cseqf, const float* __restrict__ cseqb,
                            const int* __restrict__ len,
                            float* __restrict__ h_slot, float* __restrict__ c_slot,
                            int* __restrict__ slotpos, int* __restrict__ rowOf)
{
    int idx = blockIdx.x * 256 + threadIdx.x;        // NB*NL*ND2
    int j = idx % ND2;
    int t2 = idx / ND2;
    int m = t2 % NL;
    int b = t2 / NL;
    float hv, cv;
    if (j < NH) {
        long s = ((long)b * NL + m) * NH + j;
        hv = hseqf[s]; cv = cseqf[s];
    } else {
        int ln = len[b];
        int rm = (m < ln) ? (ln - 1 - m) : m;
        long s = ((long)b * NL + rm) * NH + (j - NH);
        hv = hseqb[s]; cv = cseqb[s];
    }
    long so = ((long)b * NSLOT + m) * ND2 + j;
    h_slot[so] = hv;
    c_slot[so] = cv;
    if (j == 0) {
        slotpos[b * 16 + m] = m;
        rowOf[b * NSLOT + m] = b * NSLOT + m;   // leaves: identity row
    }
}

// build per-side gathered row lists for iter-0 (count = len-1 per batch per side)
__global__ void build_rows_k(const int* __restrict__ len, int* __restrict__ rowPL,
                             int* __restrict__ rowPR, int* __restrict__ misc)
{
    __shared__ int offs[NB];
    int b = threadIdx.x;
    int cnt = len[b] - 1;
    offs[b] = cnt;
    __syncthreads();
    for (int d = 1; d < NB; d <<= 1) {
        int v = (b >= d) ? offs[b - d] : 0;
        __syncthreads();
        offs[b] += v;
        __syncthreads();
    }
    int start = offs[b] - cnt;
    for (int m = 0; m < cnt; m++) {
        rowPL[start + m] = b * NSLOT + m;       // positions 0..len-2
        rowPR[start + m] = b * NSLOT + m + 1;   // positions 1..len-1
    }
    int NR = offs[NB - 1];
    for (int i = NR + b; i < NB * 16; i += NB) {
        rowPL[i] = DUMMY_ROW;
        rowPR[i] = DUMMY_ROW;
    }
    if (b == 0) misc[0] = (NR + 127) & ~127;
}

// fused: per-batch serial argmax (first-max-wins, same as jnp.argmax) + slotpos
// update + recompute descriptors + rowOf for the new slot + active compaction.
// Single block, 256 threads, thread b = batch b.
__global__ void argmax_compact_k(const float* __restrict__ lg, const int* __restrict__ len,
                                 int* __restrict__ slotpos, int* __restrict__ rowOf,
                                 int* __restrict__ done,
                                 int* __restrict__ lid, int* __restrict__ rid,
                                 int* __restrict__ actlist, int* __restrict__ actrows,
                                 int* __restrict__ misc, int iter, int doCompact)
{
    __shared__ int offs[NB];
    int b = threadIdx.x;
    const int npairs = 15 - iter;
    const int nslots = 16 - iter;
    int ln = len[b];
    int sp[16];
    for (int j = 0; j < nslots; j++) sp[j] = slotpos[b * 16 + j];

    float best = -3.4e38f;
    int bi = 0;
    for (int m = 0; m < npairs; m++) {
        float v = lg[(long)b * NSLOT + sp[m]];
        if (iter + 1 + m >= ln) v -= 10000.0f;   // matches ref masking exactly
        if (v > best) { best = v; bi = m; }
    }
    int dn = (iter + 1 < ln) ? 1 : 0;
    int newid = 16 + iter;
    int srcSlot = sp[bi];
    // merged slot's data lives in the nh/nc cache row keyed by the (now dead) left slot
    int newRow = ROW_CACHE_BASE + b * NSLOT + srcSlot;
    rowOf[b * NSLOT + newid] = newRow;
    if (dn) {
        for (int j = 0; j < nslots - 1; j++)
            slotpos[b * 16 + j] = (j < bi) ? sp[j] : ((j == bi) ? newid : sp[j + 1]);
    }
    done[b] = dn;
    lid[b]  = (dn && bi >= 1) ? sp[bi - 1] : -1;
    rid[b]  = (dn && bi + 2 <= nslots - 1) ? sp[bi + 2] : -1;

    if (!doCompact) return;
    offs[b] = dn;
    __syncthreads();
    for (int s = 1; s < NB; s <<= 1) {
        int v = (b >= s) ? offs[b - s] : 0;
        __syncthreads();
        offs[b] += v;
        __syncthreads();
    }
    int total = offs[NB - 1];
    if (dn) {
        int pos = offs[b] - 1;
        actlist[pos] = b;
        actrows[pos] = newRow;
    }
    if (b >= total) actrows[b] = 0;   // pad (reads h_slot row 0; outputs unused)
    if (b == 0) {
        misc[1] = total;
        misc[2] = (total + 127) & ~127;
        misc[3] = (total + 63) & ~63;
    }
}

__global__ void gate_full0_k(const float* __restrict__ PL, const float* __restrict__ PR,
                             const float* __restrict__ c_slot, const int* __restrict__ len,
                             const float* __restrict__ bcomp, const float* __restrict__ wq,
                             float* __restrict__ nh, float* __restrict__ nc,
                             float* __restrict__ lg)
{
    int blk = blockIdx.x;
    int b = blk / 15;
    int m = blk - b * 15;
    if (m >= len[b] - 1) {
        if (threadIdx.x == 0) lg[(long)b * NSLOT + m] = -1e8f;
        return;
    }
    const float* pl = PL + ((long)b * NSLOT + m) * NG5;
    const float* pr = PR + ((long)b * NSLOT + m + 1) * NG5;
    const float* cl = c_slot + ((long)b * NSLOT + m) * ND2;
    const float* cr = cl + ND2;
    float* nhr = nh + ((long)b * NSLOT + m) * ND2;
    float* ncr = nc + ((long)b * NSLOT + m) * ND2;
    float dot = 0.0f;
    for (int d = threadIdx.x; d < ND2; d += 256) {
        float g[5];
#pragma unroll
        for (int gg = 0; gg < 5; gg++) {
            int col = gg * ND2 + d;
            g[gg] = pl[col] + pr[col] + bcomp[col];
        }
        float c = cl[d] * sigm(g[1] + 1.0f) + cr[d] * sigm(g[2] + 1.0f)
                + tanhf(g[3]) * sigm(g[0]);
        float h = sigm(g[4]) * tanhf(c);
        ncr[d] = c;
        nhr[d] = h;
        dot += h * wq[d];
    }
    __shared__ float red[8];
#pragma unroll
    for (int o = 16; o > 0; o >>= 1) dot += __shfl_down_sync(0xffffffffu, dot, o);
    if ((threadIdx.x & 31) == 0) red[threadIdx.x >> 5] = dot;
    __syncthreads();
    if (threadIdx.x < 8) {
        float s = red[threadIdx.x];
#pragma unroll
        for (int o = 4; o > 0; o >>= 1) s += __shfl_down_sync(0xffu, s, o);
        if (threadIdx.x == 0) lg[(long)b * NSLOT + m] = s;
    }
}

// fused: reduce split-K partials -> PL/PR cache for new slot, then gate the (<=2) new pairs.
// c-operands resolved through rowOf (created slots read the nc cache directly).
__global__ void gate_small2_k(const float* __restrict__ vpart,
                              float* __restrict__ PL, float* __restrict__ PR,
                              const float* __restrict__ c_slot,
                              const float* __restrict__ bcomp, const float* __restrict__ wq,
                              float* __restrict__ nh, float* __restrict__ nc,
                              float* __restrict__ lg,
                              const int* __restrict__ actlist, const int* __restrict__ misc,
                              const int* __restrict__ lid, const int* __restrict__ rid,
                              const int* __restrict__ rowOf, int newid)
{
    __shared__ float vsh[NG5];
    int blk = blockIdx.x;
    int j = blk >> 1;
    int w = blk & 1;
    if (j >= misc[1]) return;
    int b = actlist[j];
    const int side = (w == 0) ? 1 : 0;   // w=0 computes PR side, w=1 PL side
    int pk = (w == 0) ? lid[b] : rid[b];
    const bool valid = (pk >= 0);
    int pkc = valid ? pk : 0;
    float* cacheDst = (w == 0 ? PR : PL) + ((long)b * NSLOT + newid) * NG5;
    const float* partner = (w == 0 ? PL : PR) + ((long)b * NSLOT + pkc) * NG5;
    const float* vp = vpart + ((long)side * ISPLIT * NB + j) * NG5;

    for (int col = threadIdx.x; col < NG5; col += 256) {
        float s = vp[col];
#pragma unroll
        for (int sp = 1; sp < ISPLIT; sp++)
            s += vp[(long)sp * NB * NG5 + col];
        cacheDst[col] = s;
        if (valid) vsh[col] = s + partner[col] + bcomp[col];
    }
    __syncthreads();
    if (!valid) return;

    int lslot = (w == 0) ? pk : newid;
    int rslot = (w == 0) ? newid : pk;
    int outkey = lslot;
    const float* cl = c_slot + (long)rowOf[b * NSLOT + lslot] * ND2;
    const float* cr = c_slot + (long)rowOf[b * NSLOT + rslot] * ND2;
    float* nhr = nh + ((long)b * NSLOT + outkey) * ND2;
    float* ncr = nc + ((long)b * NSLOT + outkey) * ND2;
    float dot = 0.0f;
    for (int d = threadIdx.x; d < ND2; d += 256) {
        float g0 = vsh[d];
        float g1 = vsh[ND2 + d];
        float g2 = vsh[2 * ND2 + d];
        float g3 = vsh[3 * ND2 + d];
        float g4 = vsh[4 * ND2 + d];
        float c = cl[d] * sigm(g1 + 1.0f) + cr[d] * sigm(g2 + 1.0f) + tanhf(g3) * sigm(g0);
        float h = sigm(g4) * tanhf(c);
        ncr[d] = c;
        nhr[d] = h;
        dot += h * wq[d];
    }
    __shared__ float red[8];
#pragma unroll
    for (int o = 16; o > 0; o >>= 1) dot += __shfl_down_sync(0xffffffffu, dot, o);
    if ((threadIdx.x & 31) == 0) red[threadIdx.x >> 5] = dot;
    __syncthreads();
    if (threadIdx.x < 8) {
        float s = red[threadIdx.x];
#pragma unroll
        for (int o = 4; o > 0; o >>= 1) s += __shfl_down_sync(0xffu, s, o);
        if (threadIdx.x == 0) lg[(long)b * NSLOT + outkey] = s;
    }
}

__global__ void copy_out2_k(const float* __restrict__ h_slot, const int* __restrict__ slotpos,
                            const int* __restrict__ rowOf, float* __restrict__ out)
{
    int idx = blockIdx.x * 256 + threadIdx.x;        // NB*ND2
    int b = idx >> 10;
    int d = idx & (ND2 - 1);
    int sp0 = slotpos[b * 16];
    out[idx] = h_slot[(long)rowOf[b * NSLOT + sp0] * ND2 + d];
}

// ---------------- launch ----------------
extern "C" void kernel_launch(void* const* d_in, const int* in_sizes, int n_in,
                              void* d_out, int out_size)
{
    const float* x       = (const float*)d_in[0];
    const int*   len     = (const int*)d_in[1];
    const float* w_ih_f  = (const float*)d_in[2];
    const float* w_hh_f  = (const float*)d_in[3];
    const float* b_f     = (const float*)d_in[4];
    const float* w_ih_b  = (const float*)d_in[5];
    const float* w_hh_b  = (const float*)d_in[6];
    const float* b_b     = (const float*)d_in[7];
    const float* w_comp  = (const float*)d_in[8];
    const float* b_comp  = (const float*)d_in[9];
    const float* w_query = (const float*)d_in[10];
    float* out = (float*)d_out;

    float* S = nullptr;
    cudaGetSymbolAddress((void**)&S, g_buf);
    int* posp = nullptr;    cudaGetSymbolAddress((void**)&posp, g_slotpos);
    int* donep = nullptr;   cudaGetSymbolAddress((void**)&donep, g_done);
    int* lidp = nullptr;    cudaGetSymbolAddress((void**)&lidp, g_lid);
    int* ridp = nullptr;    cudaGetSymbolAddress((void**)&ridp, g_rid);
    int* rowOfp = nullptr;  cudaGetSymbolAddress((void**)&rowOfp, g_rowOf);
    int* rowPLp = nullptr;  cudaGetSymbolAddress((void**)&rowPLp, g_rowPL);
    int* rowPRp = nullptr;  cudaGetSymbolAddress((void**)&rowPRp, g_rowPR);
    int* actlp = nullptr;   cudaGetSymbolAddress((void**)&actlp, g_actlist);
    int* actrp = nullptr;   cudaGetSymbolAddress((void**)&actrp, g_actrows);
    int* miscp = nullptr;   cudaGetSymbolAddress((void**)&miscp, g_misc);

    float* h_slot = S + OFF_HSLOT;
    float* c_slot = S + OFF_CSLOT;
    float* PLp = S + OFF_PL;
    float* PRp = S + OFF_PR;
    float* nhp = S + OFF_NH;
    float* ncp = S + OFF_NC;
    float* lgp = S + OFF_LG;
    float* vpart = S + OFF_VPART;

    // zero LSTM states (h_f, h_b, c_f, c_b)
    fill0_k<<<(int)((4 * SZ_ST + 255) / 256), 256>>>(S + OFF_HST, 4 * SZ_ST);

    // reversed input for backward LSTM; iter-0 per-side gathered row lists
    rev_input_k<<<(NB * NL * NH) / 256, 256>>>(x, len, S + OFF_XREV);
    build_rows_k<<<1, NB>>>(len, rowPLp, rowPRp, miscp);

    // input projections (fwd+bwd fused, standalone — NOT on the recurrent critical path)
    dim3 gproj(NG4 / 128, (NB * NL) / 128, 2);
    sgemm_proj_k<<<gproj, 256>>>(x, S + OFF_XREV, w_ih_f, w_ih_b, b_f, b_b,
                                 S + OFF_XG_F, S + OFF_XG_B);

    // recurrent steps (scalar fp32 split-K + fused cell)
    dim3 grec(NG4 / 128, NB / 128, 2 * RSPLIT);
    for (int t = 0; t < NL; t++) {
        sgemm_rec_k<<<grec, 256>>>(S + OFF_HST + 0 * SZ_ST, S + OFF_HST + 1 * SZ_ST,
                                   w_hh_f, w_hh_b, S + OFF_GPART);
        lstm_cell2_k<<<(2 * NB * NH) / 256, 256>>>(S + OFF_XG_F + (long)t * NG4,
                                                   S + OFF_XG_B + (long)t * NG4,
                                                   S + OFF_GPART,
                                                   S + OFF_HST + 0 * SZ_ST, S + OFF_HST + 1 * SZ_ST,
                                                   S + OFF_HST + 2 * SZ_ST, S + OFF_HST + 3 * SZ_ST,
                                                   S + OFF_HSEQ_F, S + OFF_HSEQ_B,
                                                   S + OFF_CSEQ_F, S + OFF_CSEQ_B, t);
    }

    // leaf slots + leaf rowOf
    tree_init_k<<<(NB * NL * ND2) / 256, 256>>>(S + OFF_HSEQ_F, S + OFF_HSEQ_B,
                                                S + OFF_CSEQ_F, S + OFF_CSEQ_B,
                                                len, h_slot, c_slot, posp, rowOfp);

    // iter-0: per-side gathered slot partials + valid-pair gates
    dim3 gs0(NG5 / 128, (NB * 16) / 128, 2);
    sgemm_slots0_k<<<gs0, 256>>>(h_slot, w_comp, PLp, PRp, rowPLp, rowPRp, miscp);
    gate_full0_k<<<NB * 15, 256>>>(PLp, PRp, c_slot, len, b_comp, w_query, nhp, ncp, lgp);

    for (int i = 0; i < 15; i++) {
        int newid = 16 + i;
        argmax_compact_k<<<1, NB>>>(lgp, len, posp, rowOfp, donep, lidp, ridp,
                                    actlp, actrp, miscp, i, (i < 14) ? 1 : 0);
        if (i < 14) {
            dim3 gi(NG5 / 128, NB / 64, 2 * ISPLIT);
            sgemm_inc64_k<<<gi, 256>>>(h_slot, w_comp, vpart, actrp, miscp);
            gate_small2_k<<<2 * NB, 256>>>(vpart, PLp, PRp, c_slot, b_comp, w_query,
                                           nhp, ncp, lgp, actlp, miscp, lidp, ridp,
                                           rowOfp, newid);
        }
    }

    copy_out2_k<<<(NB * ND2) / 256, 256>>>(h_slot, posp, rowOfp, out);
}

// round 14
// speedup vs baseline: 1.1131x; 1.1131x over previous
#include <cuda_runtime.h>

// ---------------- problem constants ----------------
constexpr int NB  = 256;   // batch
constexpr int NL  = 16;    // max length
constexpr int NH  = 512;   // LSTM hidden
constexpr int ND2 = 1024;  // 2*NH
constexpr int NG4 = 2048;  // 4*NH (lstm gates) == 2*ND2
constexpr int NG5 = 5120;  // 5*ND2 (tree gates)
constexpr int NSLOT = 31;  // 16 initial + 15 created slots (stable ids)
constexpr int RSPLIT = 4;  // recurrent GEMM split-K
constexpr int ISPLIT = 4;  // incremental GEMM split-K
constexpr int DUMMY_ROW = NB * NSLOT;   // padding target row

// ---------------- scratch layout ----------------
constexpr long SZ_XREV  = (long)NB * NL * NH;
constexpr long SZ_XG    = (long)NB * NL * NG4;
constexpr long SZ_GPART = (long)2 * RSPLIT * NB * NG4;
constexpr long SZ_ST    = (long)NB * NH;
constexpr long SZ_SEQ   = (long)NB * NL * NH;
constexpr long SZ_SLOT  = (long)NB * NSLOT * ND2;        // h_slot / c_slot / nh / nc
constexpr long SZ_P     = (long)(NB * NSLOT + 1) * NG5;  // PL / PR (+1 dummy row)
constexpr long SZ_LG    = (long)NB * NSLOT;
constexpr long SZ_VPART = (long)2 * ISPLIT * NB * NG5;

constexpr long OFF_XREV   = 0;
constexpr long OFF_XG_F   = OFF_XREV + SZ_XREV;
constexpr long OFF_XG_B   = OFF_XG_F + SZ_XG;
constexpr long OFF_GPART  = OFF_XG_B + SZ_XG;
constexpr long OFF_HST    = OFF_GPART + SZ_GPART;   // 4 states: h_f, h_b, c_f, c_b
constexpr long OFF_HSEQ_F = OFF_HST + 4 * SZ_ST;
constexpr long OFF_HSEQ_B = OFF_HSEQ_F + SZ_SEQ;
constexpr long OFF_CSEQ_F = OFF_HSEQ_B + SZ_SEQ;
constexpr long OFF_CSEQ_B = OFF_CSEQ_F + SZ_SEQ;
// h_slot, c_slot, nh, nc MUST be contiguous in this order: the rowOf indirection
// relies on  h_slot + 2*SZ_SLOT == nh  and  c_slot + 2*SZ_SLOT == nc.
constexpr long OFF_HSLOT  = OFF_CSEQ_B + SZ_SEQ;
constexpr long OFF_CSLOT  = OFF_HSLOT + SZ_SLOT;
constexpr long OFF_NH     = OFF_CSLOT + SZ_SLOT;
constexpr long OFF_NC     = OFF_NH + SZ_SLOT;
constexpr long OFF_PL     = OFF_NC + SZ_SLOT;
constexpr long OFF_PR     = OFF_PL + SZ_P;
constexpr long OFF_LG     = OFF_PR + SZ_P;
constexpr long OFF_VPART  = OFF_LG + SZ_LG;
constexpr long TOTAL_F    = OFF_VPART + SZ_VPART;

constexpr int ROW_CACHE_BASE = 2 * NB * NSLOT;   // nh/nc rows start here (relative to h_slot/c_slot)

__device__ float g_buf[TOTAL_F];
__device__ int   g_slotpos[NB * 16];     // position -> slot id
__device__ int   g_done[NB];
__device__ int   g_lid[NB];              // left-neighbor slot id for recompute pair (or -1)
__device__ int   g_rid[NB];              // right-neighbor slot id for recompute pair (or -1)
__device__ int   g_rowOf[NB * NSLOT];    // slot id -> data row (h_slot/c_slot base)
__device__ int   g_rowPL[NB * 16];       // iter-0 gathered rows, PL side (m < len-1)
__device__ int   g_rowPR[NB * 16];       // iter-0 gathered rows, PR side (1 <= m < len)
__device__ int   g_actlist[NB];          // compacted active batch ids
__device__ int   g_actrows[NB];          // compacted active data rows (for inc GEMM A gather)
__device__ int   g_misc[4];              // [0]=nrPad (iter-0), [1]=nact, [2]=nactPad

__device__ __forceinline__ float sigm(float x) { return 1.0f / (1.0f + expf(-x)); }

// ---------------- generic fp32 SGEMM body (double-buffered, KB=16, scalar FFMA) ----------------
// C[row, col] = sum_{k in [kbeg,kend)} Arow(row)[k] * W[col, k]  (+ bias[col])
// A row:  rowA ? A + rowA[r]*strideM : A + (r/P)*strideB + (r%P)*strideM
// C row:  rowC ? C + rowC[row]*N     : C + (row/P)*coStrideB + (row%P)*N
// Tiles 128x128x16, 8x8 per-thread, 256 threads. (kend-kbeg) multiple of 16.
__device__ __forceinline__
void sgemm_body(const float* __restrict__ A, int P, long strideB, long strideM,
                const int* __restrict__ rowA,
                const float* __restrict__ W, int wstride, int kbeg, int kend,
                const float* __restrict__ bias,
                float* __restrict__ C, int N, long coStrideB,
                const int* __restrict__ rowC)
{
    __shared__ float As[2][16][128];
    __shared__ float Bs[2][16][128];
    const int tid = threadIdx.x;
    const int rowBase = blockIdx.y * 128;
    const int colBase = blockIdx.x * 128;
    const int tx = tid & 15;
    const int ty = tid >> 4;
    const int lr = tid >> 1;          // load row within tile (0..127)
    const int lk = (tid & 1) * 4;     // k offset (0 or 4); second half at +8

    const int r = rowBase + lr;
    const float* aPtr;
    if (rowA) {
        aPtr = A + (long)rowA[r] * strideM + kbeg + lk;
    } else {
        const int bidx = r / P;
        aPtr = A + (long)bidx * strideB + (long)(r - bidx * P) * strideM + kbeg + lk;
    }
    const float* wPtr = W + (long)(colBase + lr) * wstride + kbeg + lk;

    float acc[8][8];
#pragma unroll
    for (int i = 0; i < 8; i++)
#pragma unroll
        for (int j = 0; j < 8; j++) acc[i][j] = 0.0f;

    const int nk = (kend - kbeg) / 16;
    float4 av0 = *reinterpret_cast<const float4*>(aPtr);
    float4 av1 = *reinterpret_cast<const float4*>(aPtr + 8);
    float4 bv0 = *reinterpret_cast<const float4*>(wPtr);
    float4 bv1 = *reinterpret_cast<const float4*>(wPtr + 8);
    int buf = 0;

    for (int it = 0; it < nk; it++) {
        As[buf][lk + 0][lr] = av0.x; As[buf][lk + 1][lr] = av0.y;
        As[buf][lk + 2][lr] = av0.z; As[buf][lk + 3][lr] = av0.w;
        As[buf][lk + 8][lr] = av1.x; As[buf][lk + 9][lr] = av1.y;
        As[buf][lk + 10][lr] = av1.z; As[buf][lk + 11][lr] = av1.w;
        Bs[buf][lk + 0][lr] = bv0.x; Bs[buf][lk + 1][lr] = bv0.y;
        Bs[buf][lk + 2][lr] = bv0.z; Bs[buf][lk + 3][lr] = bv0.w;
        Bs[buf][lk + 8][lr] = bv1.x; Bs[buf][lk + 9][lr] = bv1.y;
        Bs[buf][lk + 10][lr] = bv1.z; Bs[buf][lk + 11][lr] = bv1.w;
        __syncthreads();
        if (it + 1 < nk) {
            const int kb = (it + 1) * 16;
            av0 = *reinterpret_cast<const float4*>(aPtr + kb);
            av1 = *reinterpret_cast<const float4*>(aPtr + kb + 8);
            bv0 = *reinterpret_cast<const float4*>(wPtr + kb);
            bv1 = *reinterpret_cast<const float4*>(wPtr + kb + 8);
        }
#pragma unroll
        for (int kk = 0; kk < 16; kk++) {
            float4 a0 = *reinterpret_cast<const float4*>(&As[buf][kk][ty * 8]);
            float4 a1 = *reinterpret_cast<const float4*>(&As[buf][kk][ty * 8 + 4]);
            float4 b0 = *reinterpret_cast<const float4*>(&Bs[buf][kk][tx * 8]);
            float4 b1 = *reinterpret_cast<const float4*>(&Bs[buf][kk][tx * 8 + 4]);
            float ra[8] = {a0.x, a0.y, a0.z, a0.w, a1.x, a1.y, a1.z, a1.w};
            float rb[8] = {b0.x, b0.y, b0.z, b0.w, b1.x, b1.y, b1.z, b1.w};
#pragma unroll
            for (int i = 0; i < 8; i++)
#pragma unroll
                for (int j = 0; j < 8; j++)
                    acc[i][j] += ra[i] * rb[j];
        }
        buf ^= 1;
    }

#pragma unroll
    for (int i = 0; i < 8; i++) {
        const int row = rowBase + ty * 8 + i;
        long rOff;
        if (rowC) {
            rOff = (long)rowC[row] * N;
        } else {
            const int ob = row / P;
            rOff = (long)ob * coStrideB + (long)(row - ob * P) * N;
        }
#pragma unroll
        for (int j = 0; j < 8; j += 4) {
            const int col = colBase + tx * 8 + j;
            float4 v;
            v.x = acc[i][j]; v.y = acc[i][j + 1]; v.z = acc[i][j + 2]; v.w = acc[i][j + 3];
            if (bias) {
                v.x += bias[col]; v.y += bias[col + 1];
                v.z += bias[col + 2]; v.w += bias[col + 3];
            }
            *reinterpret_cast<float4*>(C + rOff + col) = v;
        }
    }
}

// full input projections: z selects fwd/bwd (standalone, saturated; NOT fused with rec)
__global__ __launch_bounds__(256, 2)
void sgemm_proj_k(const float* __restrict__ A0, const float* __restrict__ A1,
                  const float* __restrict__ W0, const float* __restrict__ W1,
                  const float* __restrict__ b0, const float* __restrict__ b1,
                  float* __restrict__ C0, float* __restrict__ C1)
{
    if (blockIdx.z == 0)
        sgemm_body(A0, 1, NH, 0, nullptr, W0, NH, 0, NH, b0, C0, NG4, NG4, nullptr);
    else
        sgemm_body(A1, 1, NH, 0, nullptr, W1, NH, 0, NH, b1, C1, NG4, NG4, nullptr);
}

// recurrent: z = dir*RSPLIT + sp, K=512 split into 128-chunks, partials out
__global__ __launch_bounds__(256, 2)
void sgemm_rec_k(const float* __restrict__ hf, const float* __restrict__ hb,
                 const float* __restrict__ whf, const float* __restrict__ whb,
                 float* __restrict__ gpart)
{
    const int z = blockIdx.z;
    const int dir = z / RSPLIT;
    const int sp = z % RSPLIT;
    const int kb = sp * (NH / RSPLIT);
    sgemm_body(dir ? hb : hf, 1, NH, 0, nullptr, dir ? whb : whf, NH, kb, kb + NH / RSPLIT,
               nullptr, gpart + (long)z * NB * NG4, NG4, NG4, nullptr);
}

// iter-0 slot partials over per-side gathered rows. z = side (0=PL, 1=PR).
__global__ __launch_bounds__(256, 2)
void sgemm_slots0_k(const float* __restrict__ h_slot, const float* __restrict__ w_comp,
                    float* __restrict__ PL, float* __restrict__ PR,
                    const int* __restrict__ rowPL, const int* __restrict__ rowPR,
                    const int* __restrict__ misc)
{
    if (blockIdx.y * 128 >= misc[0]) return;
    const int side = blockIdx.z;
    const int* rows = side ? rowPR : rowPL;
    sgemm_body(h_slot, 1, 0, ND2, rows,
               w_comp + side * ND2, NG4, 0, ND2, nullptr,
               side ? PR : PL, NG5, 0, rows);
}

// incremental slot partials over compacted active rows (gathered via rowOf-derived
// actrows, which point directly at the nh cache rows — no materialization needed).
__global__ __launch_bounds__(256, 2)
void sgemm_inc_k(const float* __restrict__ h_slot, const float* __restrict__ w_comp,
                 float* __restrict__ vpart, const int* __restrict__ actrows,
                 const int* __restrict__ misc)
{
    if (blockIdx.y * 128 >= misc[2]) return;
    const int z = blockIdx.z;
    const int side = z / ISPLIT;
    const int sp = z % ISPLIT;
    const int kb = sp * (ND2 / ISPLIT);
    sgemm_body(h_slot, 1, 0, ND2, actrows,
               w_comp + side * ND2, NG4, kb, kb + ND2 / ISPLIT, nullptr,
               vpart + (long)z * NB * NG5, NG5, NG5, nullptr);
}

// ---------------- helper kernels ----------------
__global__ void fill0_k(float* p, long n) {
    long i = (long)blockIdx.x * 256 + threadIdx.x;
    if (i < n) p[i] = 0.0f;
}

__global__ void rev_input_k(const float* __restrict__ x, const int* __restrict__ len,
                            float* __restrict__ xrev)
{
    int idx = blockIdx.x * 256 + threadIdx.x;        // NB*NL*NH
    int j = idx % NH;
    int t2 = idx / NH;
    int t = t2 % NL;
    int b = t2 / NL;
    int ln = len[b];
    int src = (t < ln) ? (ln - 1 - t) : t;
    xrev[idx] = x[((long)b * NL + src) * NH + j];
}

// fused fwd+bwd LSTM cell with split-K partial reduction
__global__ void lstm_cell2_k(const float* __restrict__ xgf, const float* __restrict__ xgb,
                             const float* __restrict__ gpart,
                             float* __restrict__ hf, float* __restrict__ hb,
                             float* __restrict__ cf, float* __restrict__ cb,
                             float* __restrict__ hsf, float* __restrict__ hsb,
                             float* __restrict__ csf, float* __restrict__ csb, int t)
{
    int gidx = blockIdx.x * 256 + threadIdx.x;       // 2*NB*NH
    int dir = gidx >= NB * NH;
    int idx = gidx - dir * NB * NH;
    int b = idx >> 9;
    int j = idx & (NH - 1);
    const float* xg = (dir ? xgb : xgf) + (long)b * NL * NG4;
    const float* gp = gpart + (long)dir * RSPLIT * NB * NG4 + (long)b * NG4;
    float g[4];
#pragma unroll
    for (int c4 = 0; c4 < 4; c4++) {
        int comp = c4 * NH + j;
        float s = xg[comp];
#pragma unroll
        for (int sp = 0; sp < RSPLIT; sp++)
            s += gp[(long)sp * NB * NG4 + comp];
        g[c4] = s;
    }
    float* hstate = dir ? hb : hf;
    float* cstate = dir ? cb : cf;
    float* hseq   = dir ? hsb : hsf;
    float* cseq   = dir ? csb : csf;
    float c = sigm(g[1]) * cstate[idx] + sigm(g[0]) * tanhf(g[2]);
    float h = sigm(g[3]) * tanhf(c);
    cstate[idx] = c;
    hstate[idx] = h;
    long s = ((long)b * NL + t) * NH + j;
    hseq[s] = h;
    cseq[s] = c;
}

// init slot h/c (slots 0..15 = leaf positions), position->slot map, leaf rowOf
__global__ void tree_init_k(const float* __restrict__ hseqf, const float* __restrict__ hseqb,
                            const float* __restrict__ cseqf, const float* __restrict__ cseqb,
                            const int* __restrict__ len,
                            float* __restrict__ h_slot, float* __restrict__ c_slot,
                            int* __restrict__ slotpos, int* __restrict__ rowOf)
{
    int idx = blockIdx.x * 256 + threadIdx.x;        // NB*NL*ND2
    int j = idx % ND2;
    int t2 = idx / ND2;
    int m = t2 % NL;
    int b = t2 / NL;
    float hv, cv;
    if (j < NH) {
        long s = ((long)b * NL + m) * NH + j;
        hv = hseqf[s]; cv = cseqf[s];
    } else {
        int ln = len[b];
        int rm = (m < ln) ? (ln - 1 - m) : m;
        long s = ((long)b * NL + rm) * NH + (j - NH);
        hv = hseqb[s]; cv = cseqb[s];
    }
    long so = ((long)b * NSLOT + m) * ND2 + j;
    h_slot[so] = hv;
    c_slot[so] = cv;
    if (j == 0) {
        slotpos[b * 16 + m] = m;
        rowOf[b * NSLOT + m] = b * NSLOT + m;   // leaves: identity row
    }
}

// build per-side gathered row lists for iter-0 (count = len-1 per batch per side)
__global__ void build_rows_k(const int* __restrict__ len, int* __restrict__ rowPL,
                             int* __restrict__ rowPR, int* __restrict__ misc)
{
    __shared__ int offs[NB];
    int b = threadIdx.x;
    int cnt = len[b] - 1;
    offs[b] = cnt;
    __syncthreads();
    for (int d = 1; d < NB; d <<= 1) {
        int v = (b >= d) ? offs[b - d] : 0;
        __syncthreads();
        offs[b] += v;
        __syncthreads();
    }
    int start = offs[b] - cnt;
    for (int m = 0; m < cnt; m++) {
        rowPL[start + m] = b * NSLOT + m;       // positions 0..len-2
        rowPR[start + m] = b * NSLOT + m + 1;   // positions 1..len-1
    }
    int NR = offs[NB - 1];
    for (int i = NR + b; i < NB * 16; i += NB) {
        rowPL[i] = DUMMY_ROW;
        rowPR[i] = DUMMY_ROW;
    }
    if (b == 0) misc[0] = (NR + 127) & ~127;
}

// fused: per-batch serial argmax (first-max-wins, same as jnp.argmax) + slotpos
// update + recompute descriptors + rowOf for the new slot + active compaction.
// Single block, 256 threads, thread b = batch b.
__global__ void argmax_compact_k(const float* __restrict__ lg, const int* __restrict__ len,
                                 int* __restrict__ slotpos, int* __restrict__ rowOf,
                                 int* __restrict__ done,
                                 int* __restrict__ lid, int* __restrict__ rid,
                                 int* __restrict__ actlist, int* __restrict__ actrows,
                                 int* __restrict__ misc, int iter, int doCompact)
{
    __shared__ int offs[NB];
    int b = threadIdx.x;
    const int npairs = 15 - iter;
    const int nslots = 16 - iter;
    int ln = len[b];
    int sp[16];
    for (int j = 0; j < nslots; j++) sp[j] = slotpos[b * 16 + j];

    float best = -3.4e38f;
    int bi = 0;
    for (int m = 0; m < npairs; m++) {
        float v = lg[(long)b * NSLOT + sp[m]];
        if (iter + 1 + m >= ln) v -= 10000.0f;   // matches ref masking exactly
        if (v > best) { best = v; bi = m; }
    }
    int dn = (iter + 1 < ln) ? 1 : 0;
    int newid = 16 + iter;
    int srcSlot = sp[bi];
    // merged slot's data lives in the nh/nc cache row keyed by the (now dead) left slot
    int newRow = ROW_CACHE_BASE + b * NSLOT + srcSlot;
    rowOf[b * NSLOT + newid] = newRow;
    if (dn) {
        for (int j = 0; j < nslots - 1; j++)
            slotpos[b * 16 + j] = (j < bi) ? sp[j] : ((j == bi) ? newid : sp[j + 1]);
    }
    done[b] = dn;
    lid[b]  = (dn && bi >= 1) ? sp[bi - 1] : -1;
    rid[b]  = (dn && bi + 2 <= nslots - 1) ? sp[bi + 2] : -1;

    if (!doCompact) return;
    offs[b] = dn;
    __syncthreads();
    for (int s = 1; s < NB; s <<= 1) {
        int v = (b >= s) ? offs[b - s] : 0;
        __syncthreads();
        offs[b] += v;
        __syncthreads();
    }
    int total = offs[NB - 1];
    if (dn) {
        int pos = offs[b] - 1;
        actlist[pos] = b;
        actrows[pos] = newRow;
    }
    if (b >= total) actrows[b] = 0;   // pad (reads h_slot row 0; outputs unused)
    if (b == 0) { misc[1] = total; misc[2] = (total + 127) & ~127; }
}

__global__ void gate_full0_k(const float* __restrict__ PL, const float* __restrict__ PR,
                             const float* __restrict__ c_slot, const int* __restrict__ len,
                             const float* __restrict__ bcomp, const float* __restrict__ wq,
                             float* __restrict__ nh, float* __restrict__ nc,
                             float* __restrict__ lg)
{
    int blk = blockIdx.x;
    int b = blk / 15;
    int m = blk - b * 15;
    if (m >= len[b] - 1) {
        if (threadIdx.x == 0) lg[(long)b * NSLOT + m] = -1e8f;
        return;
    }
    const float* pl = PL + ((long)b * NSLOT + m) * NG5;
    const float* pr = PR + ((long)b * NSLOT + m + 1) * NG5;
    const float* cl = c_slot + ((long)b * NSLOT + m) * ND2;
    const float* cr = cl + ND2;
    float* nhr = nh + ((long)b * NSLOT + m) * ND2;
    float* ncr = nc + ((long)b * NSLOT + m) * ND2;
    float dot = 0.0f;
    for (int d = threadIdx.x; d < ND2; d += 256) {
        float g[5];
#pragma unroll
        for (int gg = 0; gg < 5; gg++) {
            int col = gg * ND2 + d;
            g[gg] = pl[col] + pr[col] + bcomp[col];
        }
        float c = cl[d] * sigm(g[1] + 1.0f) + cr[d] * sigm(g[2] + 1.0f)
                + tanhf(g[3]) * sigm(g[0]);
        float h = sigm(g[4]) * tanhf(c);
        ncr[d] = c;
        nhr[d] = h;
        dot += h * wq[d];
    }
    __shared__ float red[8];
#pragma unroll
    for (int o = 16; o > 0; o >>= 1) dot += __shfl_down_sync(0xffffffffu, dot, o);
    if ((threadIdx.x & 31) == 0) red[threadIdx.x >> 5] = dot;
    __syncthreads();
    if (threadIdx.x < 8) {
        float s = red[threadIdx.x];
#pragma unroll
        for (int o = 4; o > 0; o >>= 1) s += __shfl_down_sync(0xffu, s, o);
        if (threadIdx.x == 0) lg[(long)b * NSLOT + m] = s;
    }
}

// fused: reduce split-K partials -> PL/PR cache for new slot, then gate the (<=2) new pairs.
// c-operands resolved through rowOf (created slots read the nc cache directly).
__global__ void gate_small2_k(const float* __restrict__ vpart,
                              float* __restrict__ PL, float* __restrict__ PR,
                              const float* __restrict__ c_slot,
                              const float* __restrict__ bcomp, const float* __restrict__ wq,
                              float* __restrict__ nh, float* __restrict__ nc,
                              float* __restrict__ lg,
                              const int* __restrict__ actlist, const int* __restrict__ misc,
                              const int* __restrict__ lid, const int* __restrict__ rid,
                              const int* __restrict__ rowOf, int newid)
{
    __shared__ float vsh[NG5];
    int blk = blockIdx.x;
    int j = blk >> 1;
    int w = blk & 1;
    if (j >= misc[1]) return;
    int b = actlist[j];
    const int side = (w == 0) ? 1 : 0;   // w=0 computes PR side, w=1 PL side
    int pk = (w == 0) ? lid[b] : rid[b];
    const bool valid = (pk >= 0);
    int pkc = valid ? pk : 0;
    float* cacheDst = (w == 0 ? PR : PL) + ((long)b * NSLOT + newid) * NG5;
    const float* partner = (w == 0 ? PL : PR) + ((long)b * NSLOT + pkc) * NG5;
    const float* vp = vpart + ((long)side * ISPLIT * NB + j) * NG5;

    for (int col = threadIdx.x; col < NG5; col += 256) {
        float s = vp[col];
#pragma unroll
        for (int sp = 1; sp < ISPLIT; sp++)
            s += vp[(long)sp * NB * NG5 + col];
        cacheDst[col] = s;
        if (valid) vsh[col] = s + partner[col] + bcomp[col];
    }
    __syncthreads();
    if (!valid) return;

    int lslot = (w == 0) ? pk : newid;
    int rslot = (w == 0) ? newid : pk;
    int outkey = lslot;
    const float* cl = c_slot + (long)rowOf[b * NSLOT + lslot] * ND2;
    const float* cr = c_slot + (long)rowOf[b * NSLOT + rslot] * ND2;
    float* nhr = nh + ((long)b * NSLOT + outkey) * ND2;
    float* ncr = nc + ((long)b * NSLOT + outkey) * ND2;
    float dot = 0.0f;
    for (int d = threadIdx.x; d < ND2; d += 256) {
        float g0 = vsh[d];
        float g1 = vsh[ND2 + d];
        float g2 = vsh[2 * ND2 + d];
        float g3 = vsh[3 * ND2 + d];
        float g4 = vsh[4 * ND2 + d];
        float c = cl[d] * sigm(g1 + 1.0f) + cr[d] * sigm(g2 + 1.0f) + tanhf(g3) * sigm(g0);
        float h = sigm(g4) * tanhf(c);
        ncr[d] = c;
        nhr[d] = h;
        dot += h * wq[d];
    }
    __shared__ float red[8];
#pragma unroll
    for (int o = 16; o > 0; o >>= 1) dot += __shfl_down_sync(0xffffffffu, dot, o);
    if ((threadIdx.x & 31) == 0) red[threadIdx.x >> 5] = dot;
    __syncthreads();
    if (threadIdx.x < 8) {
        float s = red[threadIdx.x];
#pragma unroll
        for (int o = 4; o > 0; o >>= 1) s += __shfl_down_sync(0xffu, s, o);
        if (threadIdx.x == 0) lg[(long)b * NSLOT + outkey] = s;
    }
}

__global__ void copy_out2_k(const float* __restrict__ h_slot, const int* __restrict__ slotpos,
                            const int* __restrict__ rowOf, float* __restrict__ out)
{
    int idx = blockIdx.x * 256 + threadIdx.x;        // NB*ND2
    int b = idx >> 10;
    int d = idx & (ND2 - 1);
    int sp0 = slotpos[b * 16];
    out[idx] = h_slot[(long)rowOf[b * NSLOT + sp0] * ND2 + d];
}

// ---------------- launch ----------------
extern "C" void kernel_launch(void* const* d_in, const int* in_sizes, int n_in,
                              void* d_out, int out_size)
{
    const float* x       = (const float*)d_in[0];
    const int*   len     = (const int*)d_in[1];
    const float* w_ih_f  = (const float*)d_in[2];
    const float* w_hh_f  = (const float*)d_in[3];
    const float* b_f     = (const float*)d_in[4];
    const float* w_ih_b  = (const float*)d_in[5];
    const float* w_hh_b  = (const float*)d_in[6];
    const float* b_b     = (const float*)d_in[7];
    const float* w_comp  = (const float*)d_in[8];
    const float* b_comp  = (const float*)d_in[9];
    const float* w_query = (const float*)d_in[10];
    float* out = (float*)d_out;

    float* S = nullptr;
    cudaGetSymbolAddress((void**)&S, g_buf);
    int* posp = nullptr;    cudaGetSymbolAddress((void**)&posp, g_slotpos);
    int* donep = nullptr;   cudaGetSymbolAddress((void**)&donep, g_done);
    int* lidp = nullptr;    cudaGetSymbolAddress((void**)&lidp, g_lid);
    int* ridp = nullptr;    cudaGetSymbolAddress((void**)&ridp, g_rid);
    int* rowOfp = nullptr;  cudaGetSymbolAddress((void**)&rowOfp, g_rowOf);
    int* rowPLp = nullptr;  cudaGetSymbolAddress((void**)&rowPLp, g_rowPL);
    int* rowPRp = nullptr;  cudaGetSymbolAddress((void**)&rowPRp, g_rowPR);
    int* actlp = nullptr;   cudaGetSymbolAddress((void**)&actlp, g_actlist);
    int* actrp = nullptr;   cudaGetSymbolAddress((void**)&actrp, g_actrows);
    int* miscp = nullptr;   cudaGetSymbolAddress((void**)&miscp, g_misc);

    float* h_slot = S + OFF_HSLOT;
    float* c_slot = S + OFF_CSLOT;
    float* PLp = S + OFF_PL;
    float* PRp = S + OFF_PR;
    float* nhp = S + OFF_NH;
    float* ncp = S + OFF_NC;
    float* lgp = S + OFF_LG;
    float* vpart = S + OFF_VPART;

    // zero LSTM states (h_f, h_b, c_f, c_b)
    fill0_k<<<(int)((4 * SZ_ST + 255) / 256), 256>>>(S + OFF_HST, 4 * SZ_ST);

    // reversed input for backward LSTM; iter-0 per-side gathered row lists
    rev_input_k<<<(NB * NL * NH) / 256, 256>>>(x, len, S + OFF_XREV);
    build_rows_k<<<1, NB>>>(len, rowPLp, rowPRp, miscp);

    // input projections (fwd+bwd fused, standalone — NOT on the recurrent critical path)
    dim3 gproj(NG4 / 128, (NB * NL) / 128, 2);
    sgemm_proj_k<<<gproj, 256>>>(x, S + OFF_XREV, w_ih_f, w_ih_b, b_f, b_b,
                                 S + OFF_XG_F, S + OFF_XG_B);

    // recurrent steps (scalar fp32 split-K + fused cell)
    dim3 grec(NG4 / 128, NB / 128, 2 * RSPLIT);
    for (int t = 0; t < NL; t++) {
        sgemm_rec_k<<<grec, 256>>>(S + OFF_HST + 0 * SZ_ST, S + OFF_HST + 1 * SZ_ST,
                                   w_hh_f, w_hh_b, S + OFF_GPART);
        lstm_cell2_k<<<(2 * NB * NH) / 256, 256>>>(S + OFF_XG_F + (long)t * NG4,
                                                   S + OFF_XG_B + (long)t * NG4,
                                                   S + OFF_GPART,
                                                   S + OFF_HST + 0 * SZ_ST, S + OFF_HST + 1 * SZ_ST,
                                                   S + OFF_HST + 2 * SZ_ST, S + OFF_HST + 3 * SZ_ST,
                                                   S + OFF_HSEQ_F, S + OFF_HSEQ_B,
                                                   S + OFF_CSEQ_F, S + OFF_CSEQ_B, t);
    }

    // leaf slots + leaf rowOf
    tree_init_k<<<(NB * NL * ND2) / 256, 256>>>(S + OFF_HSEQ_F, S + OFF_HSEQ_B,
                                                S + OFF_CSEQ_F, S + OFF_CSEQ_B,
                                                len, h_slot, c_slot, posp, rowOfp);

    // iter-0: per-side gathered slot partials + valid-pair gates
    dim3 gs0(NG5 / 128, (NB * 16) / 128, 2);
    sgemm_slots0_k<<<gs0, 256>>>(h_slot, w_comp, PLp, PRp, rowPLp, rowPRp, miscp);
    gate_full0_k<<<NB * 15, 256>>>(PLp, PRp, c_slot, len, b_comp, w_query, nhp, ncp, lgp);

    for (int i = 0; i < 15; i++) {
        int newid = 16 + i;
        argmax_compact_k<<<1, NB>>>(lgp, len, posp, rowOfp, donep, lidp, ridp,
                                    actlp, actrp, miscp, i, (i < 14) ? 1 : 0);
        if (i < 14) {
            dim3 gi(NG5 / 128, NB / 128, 2 * ISPLIT);
            sgemm_inc_k<<<gi, 256>>>(h_slot, w_comp, vpart, actrp, miscp);
            gate_small2_k<<<2 * NB, 256>>>(vpart, PLp, PRp, c_slot, b_comp, w_query,
                                           nhp, ncp, lgp, actlp, miscp, lidp, ridp,
                                           rowOfp, newid);
        }
    }

    copy_out2_k<<<(NB * ND2) / 256, 256>>>(h_slot, posp, rowOfp, out);
}

// round 15
// speedup vs baseline: 1.1641x; 1.0458x over previous
#include <cuda_runtime.h>

// ---------------- problem constants ----------------
constexpr int NB  = 256;   // batch
constexpr int NL  = 16;    // max length
constexpr int NH  = 512;   // LSTM hidden
constexpr int ND2 = 1024;  // 2*NH
constexpr int NG4 = 2048;  // 4*NH (lstm gates) == 2*ND2
constexpr int NG5 = 5120;  // 5*ND2 (tree gates)
constexpr int NSLOT = 31;  // 16 initial + 15 created slots (stable ids)
constexpr int RSPLIT = 4;  // recurrent GEMM split-K
constexpr int ISPLIT = 4;  // incremental GEMM split-K
constexpr int DUMMY_ROW = NB * NSLOT;   // padding target row

// ---------------- scratch layout ----------------
constexpr long SZ_XREV  = (long)NB * NL * NH;
constexpr long SZ_XG    = (long)NB * NL * NG4;
constexpr long SZ_GPART = (long)2 * RSPLIT * NB * NG4;
constexpr long SZ_ST    = (long)NB * NH;
constexpr long SZ_SEQ   = (long)NB * NL * NH;
constexpr long SZ_SLOT  = (long)NB * NSLOT * ND2;        // h_slot / c_slot / nh / nc
constexpr long SZ_P     = (long)(NB * NSLOT + 1) * NG5;  // PL / PR (+1 dummy row)
constexpr long SZ_LG    = (long)NB * NSLOT;
constexpr long SZ_VPART = (long)2 * ISPLIT * NB * NG5;

constexpr long OFF_XREV   = 0;
constexpr long OFF_XG_F   = OFF_XREV + SZ_XREV;
constexpr long OFF_XG_B   = OFF_XG_F + SZ_XG;
constexpr long OFF_GPART  = OFF_XG_B + SZ_XG;
constexpr long OFF_HST    = OFF_GPART + SZ_GPART;   // 4 states: h_f, h_b, c_f, c_b
constexpr long OFF_HSEQ_F = OFF_HST + 4 * SZ_ST;
constexpr long OFF_HSEQ_B = OFF_HSEQ_F + SZ_SEQ;
constexpr long OFF_CSEQ_F = OFF_HSEQ_B + SZ_SEQ;
constexpr long OFF_CSEQ_B = OFF_CSEQ_F + SZ_SEQ;
// h_slot, c_slot, nh, nc MUST be contiguous in this order: the rowOf indirection
// relies on  h_slot + 2*SZ_SLOT == nh  and  c_slot + 2*SZ_SLOT == nc.
constexpr long OFF_HSLOT  = OFF_CSEQ_B + SZ_SEQ;
constexpr long OFF_CSLOT  = OFF_HSLOT + SZ_SLOT;
constexpr long OFF_NH     = OFF_CSLOT + SZ_SLOT;
constexpr long OFF_NC     = OFF_NH + SZ_SLOT;
constexpr long OFF_PL     = OFF_NC + SZ_SLOT;
constexpr long OFF_PR     = OFF_PL + SZ_P;
constexpr long OFF_LG     = OFF_PR + SZ_P;
constexpr long OFF_VPART  = OFF_LG + SZ_LG;
constexpr long TOTAL_F    = OFF_VPART + SZ_VPART;

constexpr int ROW_CACHE_BASE = 2 * NB * NSLOT;   // nh/nc rows start here (relative to h_slot/c_slot)

__device__ __align__(16) float g_buf[TOTAL_F];
__device__ int   g_slotpos[NB * 16];     // position -> slot id
__device__ int   g_done[NB];
__device__ int   g_lid[NB];              // left-neighbor slot id for recompute pair (or -1)
__device__ int   g_rid[NB];              // right-neighbor slot id for recompute pair (or -1)
__device__ int   g_rowOf[NB * NSLOT];    // slot id -> data row (h_slot/c_slot base)
__device__ int   g_rowPL[NB * 16];       // iter-0 gathered rows, PL side (m < len-1)
__device__ int   g_rowPR[NB * 16];       // iter-0 gathered rows, PR side (1 <= m < len)
__device__ int   g_actlist[NB];          // compacted active batch ids
__device__ int   g_actrows[NB];          // compacted active data rows (for inc GEMM A gather)
__device__ int   g_misc[4];              // [0]=nrPad (iter-0), [1]=nact, [2]=nactPad

__device__ __forceinline__ float sigm(float x) { return 1.0f / (1.0f + expf(-x)); }
__device__ __forceinline__ float4 ld4(const float* p) {
    return *reinterpret_cast<const float4*>(p);
}
__device__ __forceinline__ void st4(float* p, float4 v) {
    *reinterpret_cast<float4*>(p) = v;
}

// ---------------- generic fp32 SGEMM body (double-buffered, KB=16, scalar FFMA) ----------------
// C[row, col] = sum_{k in [kbeg,kend)} Arow(row)[k] * W[col, k]  (+ bias[col])
// Tiles 128x128x16, 8x8 per-thread, 256 threads. (kend-kbeg) multiple of 16.
__device__ __forceinline__
void sgemm_body(const float* __restrict__ A, int P, long strideB, long strideM,
                const int* __restrict__ rowA,
                const float* __restrict__ W, int wstride, int kbeg, int kend,
                const float* __restrict__ bias,
                float* __restrict__ C, int N, long coStrideB,
                const int* __restrict__ rowC)
{
    __shared__ float As[2][16][128];
    __shared__ float Bs[2][16][128];
    const int tid = threadIdx.x;
    const int rowBase = blockIdx.y * 128;
    const int colBase = blockIdx.x * 128;
    const int tx = tid & 15;
    const int ty = tid >> 4;
    const int lr = tid >> 1;          // load row within tile (0..127)
    const int lk = (tid & 1) * 4;     // k offset (0 or 4); second half at +8

    const int r = rowBase + lr;
    const float* aPtr;
    if (rowA) {
        aPtr = A + (long)rowA[r] * strideM + kbeg + lk;
    } else {
        const int bidx = r / P;
        aPtr = A + (long)bidx * strideB + (long)(r - bidx * P) * strideM + kbeg + lk;
    }
    const float* wPtr = W + (long)(colBase + lr) * wstride + kbeg + lk;

    float acc[8][8];
#pragma unroll
    for (int i = 0; i < 8; i++)
#pragma unroll
        for (int j = 0; j < 8; j++) acc[i][j] = 0.0f;

    const int nk = (kend - kbeg) / 16;
    float4 av0 = ld4(aPtr);
    float4 av1 = ld4(aPtr + 8);
    float4 bv0 = ld4(wPtr);
    float4 bv1 = ld4(wPtr + 8);
    int buf = 0;

    for (int it = 0; it < nk; it++) {
        As[buf][lk + 0][lr] = av0.x; As[buf][lk + 1][lr] = av0.y;
        As[buf][lk + 2][lr] = av0.z; As[buf][lk + 3][lr] = av0.w;
        As[buf][lk + 8][lr] = av1.x; As[buf][lk + 9][lr] = av1.y;
        As[buf][lk + 10][lr] = av1.z; As[buf][lk + 11][lr] = av1.w;
        Bs[buf][lk + 0][lr] = bv0.x; Bs[buf][lk + 1][lr] = bv0.y;
        Bs[buf][lk + 2][lr] = bv0.z; Bs[buf][lk + 3][lr] = bv0.w;
        Bs[buf][lk + 8][lr] = bv1.x; Bs[buf][lk + 9][lr] = bv1.y;
        Bs[buf][lk + 10][lr] = bv1.z; Bs[buf][lk + 11][lr] = bv1.w;
        __syncthreads();
        if (it + 1 < nk) {
            const int kb = (it + 1) * 16;
            av0 = ld4(aPtr + kb);
            av1 = ld4(aPtr + kb + 8);
            bv0 = ld4(wPtr + kb);
            bv1 = ld4(wPtr + kb + 8);
        }
#pragma unroll
        for (int kk = 0; kk < 16; kk++) {
            float4 a0 = ld4(&As[buf][kk][ty * 8]);
            float4 a1 = ld4(&As[buf][kk][ty * 8 + 4]);
            float4 b0 = ld4(&Bs[buf][kk][tx * 8]);
            float4 b1 = ld4(&Bs[buf][kk][tx * 8 + 4]);
            float ra[8] = {a0.x, a0.y, a0.z, a0.w, a1.x, a1.y, a1.z, a1.w};
            float rb[8] = {b0.x, b0.y, b0.z, b0.w, b1.x, b1.y, b1.z, b1.w};
#pragma unroll
            for (int i = 0; i < 8; i++)
#pragma unroll
                for (int j = 0; j < 8; j++)
                    acc[i][j] += ra[i] * rb[j];
        }
        buf ^= 1;
    }

#pragma unroll
    for (int i = 0; i < 8; i++) {
        const int row = rowBase + ty * 8 + i;
        long rOff;
        if (rowC) {
            rOff = (long)rowC[row] * N;
        } else {
            const int ob = row / P;
            rOff = (long)ob * coStrideB + (long)(row - ob * P) * N;
        }
#pragma unroll
        for (int j = 0; j < 8; j += 4) {
            const int col = colBase + tx * 8 + j;
            float4 v;
            v.x = acc[i][j]; v.y = acc[i][j + 1]; v.z = acc[i][j + 2]; v.w = acc[i][j + 3];
            if (bias) {
                v.x += bias[col]; v.y += bias[col + 1];
                v.z += bias[col + 2]; v.w += bias[col + 3];
            }
            st4(C + rOff + col, v);
        }
    }
}

// full input projections: z selects fwd/bwd (standalone, saturated; NOT fused with rec)
__global__ __launch_bounds__(256, 2)
void sgemm_proj_k(const float* __restrict__ A0, const float* __restrict__ A1,
                  const float* __restrict__ W0, const float* __restrict__ W1,
                  const float* __restrict__ b0, const float* __restrict__ b1,
                  float* __restrict__ C0, float* __restrict__ C1)
{
    if (blockIdx.z == 0)
        sgemm_body(A0, 1, NH, 0, nullptr, W0, NH, 0, NH, b0, C0, NG4, NG4, nullptr);
    else
        sgemm_body(A1, 1, NH, 0, nullptr, W1, NH, 0, NH, b1, C1, NG4, NG4, nullptr);
}

// recurrent: z = dir*RSPLIT + sp, K=512 split into 128-chunks, partials out
__global__ __launch_bounds__(256, 2)
void sgemm_rec_k(const float* __restrict__ hf, const float* __restrict__ hb,
                 const float* __restrict__ whf, const float* __restrict__ whb,
                 float* __restrict__ gpart)
{
    const int z = blockIdx.z;
    const int dir = z / RSPLIT;
    const int sp = z % RSPLIT;
    const int kb = sp * (NH / RSPLIT);
    sgemm_body(dir ? hb : hf, 1, NH, 0, nullptr, dir ? whb : whf, NH, kb, kb + NH / RSPLIT,
               nullptr, gpart + (long)z * NB * NG4, NG4, NG4, nullptr);
}

// iter-0 slot partials over per-side gathered rows. z = side (0=PL, 1=PR).
__global__ __launch_bounds__(256, 2)
void sgemm_slots0_k(const float* __restrict__ h_slot, const float* __restrict__ w_comp,
                    float* __restrict__ PL, float* __restrict__ PR,
                    const int* __restrict__ rowPL, const int* __restrict__ rowPR,
                    const int* __restrict__ misc)
{
    if (blockIdx.y * 128 >= misc[0]) return;
    const int side = blockIdx.z;
    const int* rows = side ? rowPR : rowPL;
    sgemm_body(h_slot, 1, 0, ND2, rows,
               w_comp + side * ND2, NG4, 0, ND2, nullptr,
               side ? PR : PL, NG5, 0, rows);
}

// incremental slot partials over compacted active rows (gathered via rowOf-derived
// actrows, which point directly at the nh cache rows — no materialization needed).
__global__ __launch_bounds__(256, 2)
void sgemm_inc_k(const float* __restrict__ h_slot, const float* __restrict__ w_comp,
                 float* __restrict__ vpart, const int* __restrict__ actrows,
                 const int* __restrict__ misc)
{
    if (blockIdx.y * 128 >= misc[2]) return;
    const int z = blockIdx.z;
    const int side = z / ISPLIT;
    const int sp = z % ISPLIT;
    const int kb = sp * (ND2 / ISPLIT);
    sgemm_body(h_slot, 1, 0, ND2, actrows,
               w_comp + side * ND2, NG4, kb, kb + ND2 / ISPLIT, nullptr,
               vpart + (long)z * NB * NG5, NG5, NG5, nullptr);
}

// ---------------- helper kernels (float4-vectorized elementwise) ----------------
__global__ void fill0_k(float* p, long n) {
    long i = (long)blockIdx.x * 256 + threadIdx.x;
    if (i < n) p[i] = 0.0f;
}

// float4 over NB*NL*NH/4
__global__ void rev_input_k(const float* __restrict__ x, const int* __restrict__ len,
                            float* __restrict__ xrev)
{
    int idx = blockIdx.x * 256 + threadIdx.x;
    int j4 = idx & (NH / 4 - 1);     // 128 float4 per row
    int t2 = idx >> 7;
    int t = t2 & (NL - 1);
    int b = t2 >> 4;
    int ln = len[b];
    int src = (t < ln) ? (ln - 1 - t) : t;
    st4(xrev + (long)idx * 4, ld4(x + (((long)b * NL + src) * NH) + j4 * 4));
}

// fused fwd+bwd LSTM cell with split-K partial reduction; float4 over 2*NB*NH/4
__global__ void lstm_cell2_k(const float* __restrict__ xgf, const float* __restrict__ xgb,
                             const float* __restrict__ gpart,
                             float* __restrict__ hf, float* __restrict__ hb,
                             float* __restrict__ cf, float* __restrict__ cb,
                             float* __restrict__ hsf, float* __restrict__ hsb,
                             float* __restrict__ csf, float* __restrict__ csb, int t)
{
    int gidx = blockIdx.x * 256 + threadIdx.x;       // 2*NB*NH/4
    int dir = gidx >= NB * NH / 4;
    int idx4 = gidx - dir * (NB * NH / 4);
    int b = idx4 >> 7;                               // NH/4 = 128
    int j = (idx4 & 127) * 4;
    const float* xg = (dir ? xgb : xgf) + (long)b * NL * NG4;
    const float* gp = gpart + (long)dir * RSPLIT * NB * NG4 + (long)b * NG4;
    float4 g[4];
#pragma unroll
    for (int c4 = 0; c4 < 4; c4++) {
        int comp = c4 * NH + j;
        float4 s = ld4(xg + comp);
#pragma unroll
        for (int sp = 0; sp < RSPLIT; sp++) {
            float4 pv = ld4(gp + (long)sp * NB * NG4 + comp);
            s.x += pv.x; s.y += pv.y; s.z += pv.z; s.w += pv.w;
        }
        g[c4] = s;
    }
    float* hstate = dir ? hb : hf;
    float* cstate = dir ? cb : cf;
    float* hseq   = dir ? hsb : hsf;
    float* cseq   = dir ? csb : csf;
    float4 cPrev = ld4(cstate + (long)idx4 * 4);
    float4 cv, hv;
    cv.x = sigm(g[1].x) * cPrev.x + sigm(g[0].x) * tanhf(g[2].x);
    cv.y = sigm(g[1].y) * cPrev.y + sigm(g[0].y) * tanhf(g[2].y);
    cv.z = sigm(g[1].z) * cPrev.z + sigm(g[0].z) * tanhf(g[2].z);
    cv.w = sigm(g[1].w) * cPrev.w + sigm(g[0].w) * tanhf(g[2].w);
    hv.x = sigm(g[3].x) * tanhf(cv.x);
    hv.y = sigm(g[3].y) * tanhf(cv.y);
    hv.z = sigm(g[3].z) * tanhf(cv.z);
    hv.w = sigm(g[3].w) * tanhf(cv.w);
    st4(cstate + (long)idx4 * 4, cv);
    st4(hstate + (long)idx4 * 4, hv);
    long s = ((long)b * NL + t) * NH + j;
    st4(hseq + s, hv);
    st4(cseq + s, cv);
}

// init slot h/c, position->slot map, leaf rowOf; float4 over NB*NL*ND2/4
__global__ void tree_init_k(const float* __restrict__ hseqf, const float* __restrict__ hseqb,
                            const float* __restrict__ cseqf, const float* __restrict__ cseqb,
                            const int* __restrict__ len,
                            float* __restrict__ h_slot, float* __restrict__ c_slot,
                            int* __restrict__ slotpos, int* __restrict__ rowOf)
{
    int idx = blockIdx.x * 256 + threadIdx.x;        // NB*NL*ND2/4
    int j = (idx & 255) * 4;                         // ND2/4 = 256
    int t2 = idx >> 8;
    int m = t2 & (NL - 1);
    int b = t2 >> 4;
    float4 hv, cv;
    if (j < NH) {
        long s = ((long)b * NL + m) * NH + j;
        hv = ld4(hseqf + s); cv = ld4(cseqf + s);
    } else {
        int ln = len[b];
        int rm = (m < ln) ? (ln - 1 - m) : m;
        long s = ((long)b * NL + rm) * NH + (j - NH);
        hv = ld4(hseqb + s); cv = ld4(cseqb + s);
    }
    long so = ((long)b * NSLOT + m) * ND2 + j;
    st4(h_slot + so, hv);
    st4(c_slot + so, cv);
    if (j == 0) {
        slotpos[b * 16 + m] = m;
        rowOf[b * NSLOT + m] = b * NSLOT + m;   // leaves: identity row
    }
}

// build per-side gathered row lists for iter-0 (count = len-1 per batch per side)
__global__ void build_rows_k(const int* __restrict__ len, int* __restrict__ rowPL,
                             int* __restrict__ rowPR, int* __restrict__ misc)
{
    __shared__ int offs[NB];
    int b = threadIdx.x;
    int cnt = len[b] - 1;
    offs[b] = cnt;
    __syncthreads();
    for (int d = 1; d < NB; d <<= 1) {
        int v = (b >= d) ? offs[b - d] : 0;
        __syncthreads();
        offs[b] += v;
        __syncthreads();
    }
    int start = offs[b] - cnt;
    for (int m = 0; m < cnt; m++) {
        rowPL[start + m] = b * NSLOT + m;       // positions 0..len-2
        rowPR[start + m] = b * NSLOT + m + 1;   // positions 1..len-1
    }
    int NR = offs[NB - 1];
    for (int i = NR + b; i < NB * 16; i += NB) {
        rowPL[i] = DUMMY_ROW;
        rowPR[i] = DUMMY_ROW;
    }
    if (b == 0) misc[0] = (NR + 127) & ~127;
}

// fused: per-batch serial argmax (first-max-wins, same as jnp.argmax) + slotpos
// update + recompute descriptors + rowOf for the new slot + active compaction.
__global__ void argmax_compact_k(const float* __restrict__ lg, const int* __restrict__ len,
                                 int* __restrict__ slotpos, int* __restrict__ rowOf,
                                 int* __restrict__ done,
                                 int* __restrict__ lid, int* __restrict__ rid,
                                 int* __restrict__ actlist, int* __restrict__ actrows,
                                 int* __restrict__ misc, int iter, int doCompact)
{
    __shared__ int offs[NB];
    int b = threadIdx.x;
    const int npairs = 15 - iter;
    const int nslots = 16 - iter;
    int ln = len[b];
    int sp[16];
    for (int j = 0; j < nslots; j++) sp[j] = slotpos[b * 16 + j];

    float best = -3.4e38f;
    int bi = 0;
    for (int m = 0; m < npairs; m++) {
        float v = lg[(long)b * NSLOT + sp[m]];
        if (iter + 1 + m >= ln) v -= 10000.0f;   // matches ref masking exactly
        if (v > best) { best = v; bi = m; }
    }
    int dn = (iter + 1 < ln) ? 1 : 0;
    int newid = 16 + iter;
    int srcSlot = sp[bi];
    int newRow = ROW_CACHE_BASE + b * NSLOT + srcSlot;
    rowOf[b * NSLOT + newid] = newRow;
    if (dn) {
        for (int j = 0; j < nslots - 1; j++)
            slotpos[b * 16 + j] = (j < bi) ? sp[j] : ((j == bi) ? newid : sp[j + 1]);
    }
    done[b] = dn;
    lid[b]  = (dn && bi >= 1) ? sp[bi - 1] : -1;
    rid[b]  = (dn && bi + 2 <= nslots - 1) ? sp[bi + 2] : -1;

    if (!doCompact) return;
    offs[b] = dn;
    __syncthreads();
    for (int s = 1; s < NB; s <<= 1) {
        int v = (b >= s) ? offs[b - s] : 0;
        __syncthreads();
        offs[b] += v;
        __syncthreads();
    }
    int total = offs[NB - 1];
    if (dn) {
        int pos = offs[b] - 1;
        actlist[pos] = b;
        actrows[pos] = newRow;
    }
    if (b >= total) actrows[b] = 0;   // pad (reads h_slot row 0; outputs unused)
    if (b == 0) { misc[1] = total; misc[2] = (total + 127) & ~127; }
}

// iter-0 pair gates, float4: one pass (ND2/4 == blockDim)
__global__ void gate_full0_k(const float* __restrict__ PL, const float* __restrict__ PR,
                             const float* __restrict__ c_slot, const int* __restrict__ len,
                             const float* __restrict__ bcomp, const float* __restrict__ wq,
                             float* __restrict__ nh, float* __restrict__ nc,
                             float* __restrict__ lg)
{
    int blk = blockIdx.x;
    int b = blk / 15;
    int m = blk - b * 15;
    if (m >= len[b] - 1) {
        if (threadIdx.x == 0) lg[(long)b * NSLOT + m] = -1e8f;
        return;
    }
    const float* pl = PL + ((long)b * NSLOT + m) * NG5;
    const float* pr = PR + ((long)b * NSLOT + m + 1) * NG5;
    const float* cl = c_slot + ((long)b * NSLOT + m) * ND2;
    const float* cr = cl + ND2;
    float* nhr = nh + ((long)b * NSLOT + m) * ND2;
    float* ncr = nc + ((long)b * NSLOT + m) * ND2;
    const int d = threadIdx.x * 4;                   // ND2/4 = 256 = blockDim
    float4 g[5];
#pragma unroll
    for (int gg = 0; gg < 5; gg++) {
        int col = gg * ND2 + d;
        float4 a = ld4(pl + col);
        float4 p = ld4(pr + col);
        float4 bb = ld4(bcomp + col);
        g[gg].x = a.x + p.x + bb.x;
        g[gg].y = a.y + p.y + bb.y;
        g[gg].z = a.z + p.z + bb.z;
        g[gg].w = a.w + p.w + bb.w;
    }
    float4 clv = ld4(cl + d);
    float4 crv = ld4(cr + d);
    float4 cv, hv;
    cv.x = clv.x * sigm(g[1].x + 1.0f) + crv.x * sigm(g[2].x + 1.0f) + tanhf(g[3].x) * sigm(g[0].x);
    cv.y = clv.y * sigm(g[1].y + 1.0f) + crv.y * sigm(g[2].y + 1.0f) + tanhf(g[3].y) * sigm(g[0].y);
    cv.z = clv.z * sigm(g[1].z + 1.0f) + crv.z * sigm(g[2].z + 1.0f) + tanhf(g[3].z) * sigm(g[0].z);
    cv.w = clv.w * sigm(g[1].w + 1.0f) + crv.w * sigm(g[2].w + 1.0f) + tanhf(g[3].w) * sigm(g[0].w);
    hv.x = sigm(g[4].x) * tanhf(cv.x);
    hv.y = sigm(g[4].y) * tanhf(cv.y);
    hv.z = sigm(g[4].z) * tanhf(cv.z);
    hv.w = sigm(g[4].w) * tanhf(cv.w);
    st4(ncr + d, cv);
    st4(nhr + d, hv);
    float4 wv = ld4(wq + d);
    float dot = hv.x * wv.x + hv.y * wv.y + hv.z * wv.z + hv.w * wv.w;
    __shared__ float red[8];
#pragma unroll
    for (int o = 16; o > 0; o >>= 1) dot += __shfl_down_sync(0xffffffffu, dot, o);
    if ((threadIdx.x & 31) == 0) red[threadIdx.x >> 5] = dot;
    __syncthreads();
    if (threadIdx.x < 8) {
        float s = red[threadIdx.x];
#pragma unroll
        for (int o = 4; o > 0; o >>= 1) s += __shfl_down_sync(0xffu, s, o);
        if (threadIdx.x == 0) lg[(long)b * NSLOT + m] = s;
    }
}

// fused: reduce split-K partials -> PL/PR cache for new slot, then gate the (<=2) new pairs.
// float4 throughout; c-operands resolved through rowOf.
__global__ void gate_small2_k(const float* __restrict__ vpart,
                              float* __restrict__ PL, float* __restrict__ PR,
                              const float* __restrict__ c_slot,
                              const float* __restrict__ bcomp, const float* __restrict__ wq,
                              float* __restrict__ nh, float* __restrict__ nc,
                              float* __restrict__ lg,
                              const int* __restrict__ actlist, const int* __restrict__ misc,
                              const int* __restrict__ lid, const int* __restrict__ rid,
                              const int* __restrict__ rowOf, int newid)
{
    __shared__ __align__(16) float vsh[NG5];
    int blk = blockIdx.x;
    int j = blk >> 1;
    int w = blk & 1;
    if (j >= misc[1]) return;
    int b = actlist[j];
    const int side = (w == 0) ? 1 : 0;   // w=0 computes PR side, w=1 PL side
    int pk = (w == 0) ? lid[b] : rid[b];
    const bool valid = (pk >= 0);
    int pkc = valid ? pk : 0;
    float* cacheDst = (w == 0 ? PR : PL) + ((long)b * NSLOT + newid) * NG5;
    const float* partner = (w == 0 ? PL : PR) + ((long)b * NSLOT + pkc) * NG5;
    const float* vp = vpart + ((long)side * ISPLIT * NB + j) * NG5;

    for (int c4 = threadIdx.x; c4 < NG5 / 4; c4 += 256) {
        int col = c4 * 4;
        float4 s = ld4(vp + col);
#pragma unroll
        for (int sp = 1; sp < ISPLIT; sp++) {
            float4 pv = ld4(vp + (long)sp * NB * NG5 + col);
            s.x += pv.x; s.y += pv.y; s.z += pv.z; s.w += pv.w;
        }
        st4(cacheDst + col, s);
        if (valid) {
            float4 pn = ld4(partner + col);
            float4 bb = ld4(bcomp + col);
            float4 v;
            v.x = s.x + pn.x + bb.x;
            v.y = s.y + pn.y + bb.y;
            v.z = s.z + pn.z + bb.z;
            v.w = s.w + pn.w + bb.w;
            st4(vsh + col, v);
        }
    }
    __syncthreads();
    if (!valid) return;

    int lslot = (w == 0) ? pk : newid;
    int rslot = (w == 0) ? newid : pk;
    int outkey = lslot;
    const float* cl = c_slot + (long)rowOf[b * NSLOT + lslot] * ND2;
    const float* cr = c_slot + (long)rowOf[b * NSLOT + rslot] * ND2;
    float* nhr = nh + ((long)b * NSLOT + outkey) * ND2;
    float* ncr = nc + ((long)b * NSLOT + outkey) * ND2;
    const int d = threadIdx.x * 4;                   // single pass, ND2/4 = 256
    float4 g0 = ld4(vsh + d);
    float4 g1 = ld4(vsh + ND2 + d);
    float4 g2 = ld4(vsh + 2 * ND2 + d);
    float4 g3 = ld4(vsh + 3 * ND2 + d);
    float4 g4 = ld4(vsh + 4 * ND2 + d);
    float4 clv = ld4(cl + d);
    float4 crv = ld4(cr + d);
    float4 cv, hv;
    cv.x = clv.x * sigm(g1.x + 1.0f) + crv.x * sigm(g2.x + 1.0f) + tanhf(g3.x) * sigm(g0.x);
    cv.y = clv.y * sigm(g1.y + 1.0f) + crv.y * sigm(g2.y + 1.0f) + tanhf(g3.y) * sigm(g0.y);
    cv.z = clv.z * sigm(g1.z + 1.0f) + crv.z * sigm(g2.z + 1.0f) + tanhf(g3.z) * sigm(g0.z);
    cv.w = clv.w * sigm(g1.w + 1.0f) + crv.w * sigm(g2.w + 1.0f) + tanhf(g3.w) * sigm(g0.w);
    hv.x = sigm(g4.x) * tanhf(cv.x);
    hv.y = sigm(g4.y) * tanhf(cv.y);
    hv.z = sigm(g4.z) * tanhf(cv.z);
    hv.w = sigm(g4.w) * tanhf(cv.w);
    st4(ncr + d, cv);
    st4(nhr + d, hv);
    float4 wv = ld4(wq + d);
    float dot = hv.x * wv.x + hv.y * wv.y + hv.z * wv.z + hv.w * wv.w;
    __shared__ float red[8];
#pragma unroll
    for (int o = 16; o > 0; o >>= 1) dot += __shfl_down_sync(0xffffffffu, dot, o);
    if ((threadIdx.x & 31) == 0) red[threadIdx.x >> 5] = dot;
    __syncthreads();
    if (threadIdx.x < 8) {
        float s = red[threadIdx.x];
#pragma unroll
        for (int o = 4; o > 0; o >>= 1) s += __shfl_down_sync(0xffu, s, o);
        if (threadIdx.x == 0) lg[(long)b * NSLOT + outkey] = s;
    }
}

// float4 over NB*ND2/4
__global__ void copy_out2_k(const float* __restrict__ h_slot, const int* __restrict__ slotpos,
                            const int* __restrict__ rowOf, float* __restrict__ out)
{
    int idx = blockIdx.x * 256 + threadIdx.x;        // NB*ND2/4
    int b = idx >> 8;                                // ND2/4 = 256
    int d = (idx & 255) * 4;
    int sp0 = slotpos[b * 16];
    st4(out + (long)b * ND2 + d, ld4(h_slot + (long)rowOf[b * NSLOT + sp0] * ND2 + d));
}

// ---------------- launch ----------------
extern "C" void kernel_launch(void* const* d_in, const int* in_sizes, int n_in,
                              void* d_out, int out_size)
{
    const float* x       = (const float*)d_in[0];
    const int*   len     = (const int*)d_in[1];
    const float* w_ih_f  = (const float*)d_in[2];
    const float* w_hh_f  = (const float*)d_in[3];
    const float* b_f     = (const float*)d_in[4];
    const float* w_ih_b  = (const float*)d_in[5];
    const float* w_hh_b  = (const float*)d_in[6];
    const float* b_b     = (const float*)d_in[7];
    const float* w_comp  = (const float*)d_in[8];
    const float* b_comp  = (const float*)d_in[9];
    const float* w_query = (const float*)d_in[10];
    float* out = (float*)d_out;

    float* S = nullptr;
    cudaGetSymbolAddress((void**)&S, g_buf);
    int* posp = nullptr;    cudaGetSymbolAddress((void**)&posp, g_slotpos);
    int* donep = nullptr;   cudaGetSymbolAddress((void**)&donep, g_done);
    int* lidp = nullptr;    cudaGetSymbolAddress((void**)&lidp, g_lid);
    int* ridp = nullptr;    cudaGetSymbolAddress((void**)&ridp, g_rid);
    int* rowOfp = nullptr;  cudaGetSymbolAddress((void**)&rowOfp, g_rowOf);
    int* rowPLp = nullptr;  cudaGetSymbolAddress((void**)&rowPLp, g_rowPL);
    int* rowPRp = nullptr;  cudaGetSymbolAddress((void**)&rowPRp, g_rowPR);
    int* actlp = nullptr;   cudaGetSymbolAddress((void**)&actlp, g_actlist);
    int* actrp = nullptr;   cudaGetSymbolAddress((void**)&actrp, g_actrows);
    int* miscp = nullptr;   cudaGetSymbolAddress((void**)&miscp, g_misc);

    float* h_slot = S + OFF_HSLOT;
    float* c_slot = S + OFF_CSLOT;
    float* PLp = S + OFF_PL;
    float* PRp = S + OFF_PR;
    float* nhp = S + OFF_NH;
    float* ncp = S + OFF_NC;
    float* lgp = S + OFF_LG;
    float* vpart = S + OFF_VPART;

    // zero LSTM states (h_f, h_b, c_f, c_b)
    fill0_k<<<(int)((4 * SZ_ST + 255) / 256), 256>>>(S + OFF_HST, 4 * SZ_ST);

    // reversed input for backward LSTM; iter-0 per-side gathered row lists
    rev_input_k<<<(NB * NL * NH / 4) / 256, 256>>>(x, len, S + OFF_XREV);
    build_rows_k<<<1, NB>>>(len, rowPLp, rowPRp, miscp);

    // input projections (fwd+bwd fused, standalone — NOT on the recurrent critical path)
    dim3 gproj(NG4 / 128, (NB * NL) / 128, 2);
    sgemm_proj_k<<<gproj, 256>>>(x, S + OFF_XREV, w_ih_f, w_ih_b, b_f, b_b,
                                 S + OFF_XG_F, S + OFF_XG_B);

    // recurrent steps (scalar fp32 split-K + fused cell)
    dim3 grec(NG4 / 128, NB / 128, 2 * RSPLIT);
    for (int t = 0; t < NL; t++) {
        sgemm_rec_k<<<grec, 256>>>(S + OFF_HST + 0 * SZ_ST, S + OFF_HST + 1 * SZ_ST,
                                   w_hh_f, w_hh_b, S + OFF_GPART);
        lstm_cell2_k<<<(2 * NB * NH / 4) / 256, 256>>>(S + OFF_XG_F + (long)t * NG4,
                                                       S + OFF_XG_B + (long)t * NG4,
                                                       S + OFF_GPART,
                                                       S + OFF_HST + 0 * SZ_ST, S + OFF_HST + 1 * SZ_ST,
                                                       S + OFF_HST + 2 * SZ_ST, S + OFF_HST + 3 * SZ_ST,
                                                       S + OFF_HSEQ_F, S + OFF_HSEQ_B,
                                                       S + OFF_CSEQ_F, S + OFF_CSEQ_B, t);
    }

    // leaf slots + leaf rowOf
    tree_init_k<<<(NB * NL * ND2 / 4) / 256, 256>>>(S + OFF_HSEQ_F, S + OFF_HSEQ_B,
                                                    S + OFF_CSEQ_F, S + OFF_CSEQ_B,
                                                    len, h_slot, c_slot, posp, rowOfp);

    // iter-0: per-side gathered slot partials + valid-pair gates
    dim3 gs0(NG5 / 128, (NB * 16) / 128, 2);
    sgemm_slots0_k<<<gs0, 256>>>(h_slot, w_comp, PLp, PRp, rowPLp, rowPRp, miscp);
    gate_full0_k<<<NB * 15, 256>>>(PLp, PRp, c_slot, len, b_comp, w_query, nhp, ncp, lgp);

    for (int i = 0; i < 15; i++) {
        int newid = 16 + i;
        argmax_compact_k<<<1, NB>>>(lgp, len, posp, rowOfp, donep, lidp, ridp,
                                    actlp, actrp, miscp, i, (i < 14) ? 1 : 0);
        if (i < 14) {
            dim3 gi(NG5 / 128, NB / 128, 2 * ISPLIT);
            sgemm_inc_k<<<gi, 256>>>(h_slot, w_comp, vpart, actrp, miscp);
            gate_small2_k<<<2 * NB, 256>>>(vpart, PLp, PRp, c_slot, b_comp, w_query,
                                           nhp, ncp, lgp, actlp, miscp, lidp, ridp,
                                           rowOfp, newid);
        }
    }

    copy_out2_k<<<(NB * ND2 / 4) / 256, 256>>>(h_slot, posp, rowOfp, out);
}